// round 12
// baseline (speedup 1.0000x reference)
#include <cuda_runtime.h>
#include <cuda_bf16.h>
#include <math.h>
#include <stdint.h>

#define B_   4
#define C_   2048
#define H_   48
#define N_   2304
#define CAM_ 384

#define TM   128
#define TN   128
#define TK   64
#define STAGE 32768                 /* A: 128*128B + B: 128*128B */
#define SMEM_DYN (2*STAGE + 1024)

// ---------------- scratch (device globals) ----------------------------------
__device__ __nv_bfloat16 g_xb [B_ * C_ * N_];   // x bf16  [C,N]
__device__ __nv_bfloat16 g_xt [B_ * N_ * C_];   // x^T bf16 [N,C]
__device__ __nv_bfloat16 g_wqb[C_ * C_];
__device__ __nv_bfloat16 g_wkb[C_ * C_];
__device__ __nv_bfloat16 g_qr [B_ * N_ * C_];   // q, compacted rows
__device__ __nv_bfloat16 g_kr [B_ * N_ * C_];   // k, full rows
__device__ __nv_bfloat16 g_attb[B_ * N_ * N_];  // exp(logits), compacted rows
__device__ float g_qn2[B_ * N_];
__device__ float g_kn2[B_ * N_];
__device__ float g_rsum[B_ * N_];               // rowsum(exp), fp32
__device__ int   g_mflag[B_ * N_];
__device__ int   g_idx [B_ * N_];
__device__ int   g_nact[B_];
__device__ double g_sum;
__device__ unsigned long long g_cnt;

// ---------------- helpers -----------------------------------------------------
__device__ __forceinline__ uint32_t smem_u32(const void* p) {
    uint32_t a;
    asm("{ .reg .u64 t; cvta.to.shared.u64 t, %1; cvt.u32.u64 %0, t; }"
        : "=r"(a) : "l"(p));
    return a;
}
__device__ __forceinline__ void cp_async16(uint32_t dst, const void* src) {
    asm volatile("cp.async.cg.shared.global [%0], [%1], 16;"
                 :: "r"(dst), "l"(src) : "memory");
}
__device__ __forceinline__ void cp_commit() {
    asm volatile("cp.async.commit_group;" ::: "memory");
}
__device__ __forceinline__ void cp_wait0() {
    asm volatile("cp.async.wait_group 0;" ::: "memory");
}
__device__ __forceinline__ void cp_wait1() {
    asm volatile("cp.async.wait_group 1;" ::: "memory");
}
__device__ __forceinline__ void ldsm_x4(uint32_t addr, uint32_t* r) {
    asm volatile("ldmatrix.sync.aligned.m8n8.x4.shared.b16 {%0,%1,%2,%3}, [%4];"
        : "=r"(r[0]), "=r"(r[1]), "=r"(r[2]), "=r"(r[3]) : "r"(addr));
}
__device__ __forceinline__ void mma_bf16(float* d, const uint32_t* a, const uint32_t* b) {
    asm volatile(
        "mma.sync.aligned.m16n8k16.row.col.f32.bf16.bf16.f32 "
        "{%0,%1,%2,%3}, {%4,%5,%6,%7}, {%8,%9}, {%0,%1,%2,%3};"
        : "+f"(d[0]), "+f"(d[1]), "+f"(d[2]), "+f"(d[3])
        : "r"(a[0]), "r"(a[1]), "r"(a[2]), "r"(a[3]), "r"(b[0]), "r"(b[1]));
}
#define SWZ(o) ((o) ^ (((o) >> 3) & 0x70))

// ---------------- small kernels ------------------------------------------------
__global__ void init_kernel() {
    if (blockIdx.x == 0 && threadIdx.x == 0) { g_sum = 0.0; g_cnt = 0ull; }
    int i = blockIdx.x * blockDim.x + threadIdx.x;
    if (i < B_) g_nact[i] = 0;
}

// bilinear mask + row compaction + zero accumulators (cam only; before cvt_x)
__global__ void mask_kernel(const float* __restrict__ cam) {
    int i = blockIdx.x * blockDim.x + threadIdx.x;
    if (i >= B_ * N_) return;
    g_qn2[i] = 0.f; g_kn2[i] = 0.f; g_rsum[i] = 0.f;
    int b = i / N_, p = i % N_;
    int oy = p / H_, ox = p % H_;
    const float step = 383.0f / 47.0f;
    float sy = (float)oy * step, sx = (float)ox * step;
    int y0 = min(max((int)floorf(sy), 0), CAM_ - 1);
    int x0 = min(max((int)floorf(sx), 0), CAM_ - 1);
    int y1 = min(y0 + 1, CAM_ - 1), x1 = min(x0 + 1, CAM_ - 1);
    float wy = sy - (float)y0, wx = sx - (float)x0;
    const float* cb = cam + (size_t)b * CAM_ * CAM_;
    float v00 = cb[y0 * CAM_ + x0]; v00 = (v00 == 255.0f) ? 0.f : v00;
    float v01 = cb[y0 * CAM_ + x1]; v01 = (v01 == 255.0f) ? 0.f : v01;
    float v10 = cb[y1 * CAM_ + x0]; v10 = (v10 == 255.0f) ? 0.f : v10;
    float v11 = cb[y1 * CAM_ + x1]; v11 = (v11 == 255.0f) ? 0.f : v11;
    float val = (1.f - wy) * ((1.f - wx) * v00 + wx * v01)
              + wy * ((1.f - wx) * v10 + wx * v11);
    if (val > 0.f) {
        g_mflag[i] = 1;
        int slot = atomicAdd(&g_nact[b], 1);
        g_idx[b * N_ + slot] = p;
    } else {
        g_mflag[i] = 0;
    }
}

// x fp32 [C,N] -> g_xb bf16 [C,N], g_xt bf16 [N,C]; masked-row loss, atomic-free
__global__ void cvt_x_kernel(const float* __restrict__ x) {
    __shared__ float tile[64][33];
    __shared__ float ssum[8][64];
    __shared__ int   scnt[8][64];
    __shared__ float rsum[64];
    __shared__ int   rcnt[64];
    const int b = blockIdx.z;
    const int n0 = blockIdx.x * 64, c0 = blockIdx.y * 32;
    const int tx = threadIdx.x, ty = threadIdx.y;   // 32 x 8
    const int tid = ty * 32 + tx;
    const float* xp = x + (size_t)b * C_ * N_;
    __nv_bfloat16* xbp = g_xb + (size_t)b * C_ * N_;
    __nv_bfloat16* xtp = g_xt + (size_t)b * N_ * C_;

    float s0 = 0.f, s1 = 0.f;
    int   k0 = 0,   k1 = 0;
    #pragma unroll
    for (int r = 0; r < 4; r++) {
        int c = c0 + ty + r * 8;
        float2 v = *(const float2*)(xp + (size_t)c * N_ + n0 + tx * 2);
        tile[tx * 2][ty + r * 8]     = v.x;
        tile[tx * 2 + 1][ty + r * 8] = v.y;
        *(__nv_bfloat162*)(xbp + (size_t)c * N_ + n0 + tx * 2) =
            __floats2bfloat162_rn(v.x, v.y);
        s0 += v.x * v.x; k0 += (v.x != 0.f);
        s1 += v.y * v.y; k1 += (v.y != 0.f);
    }
    ssum[ty][tx * 2] = s0; ssum[ty][tx * 2 + 1] = s1;
    scnt[ty][tx * 2] = k0; scnt[ty][tx * 2 + 1] = k1;
    __syncthreads();

    const int half = tx >> 4, cp2 = (tx & 15) * 2;
    #pragma unroll
    for (int r = 0; r < 4; r++) {
        int nl = ty * 2 + half + r * 16;
        *(__nv_bfloat162*)(xtp + (size_t)(n0 + nl) * C_ + c0 + cp2) =
            __floats2bfloat162_rn(tile[nl][cp2], tile[nl][cp2 + 1]);
    }
    if (tid < 64) {
        float s = 0.f; int k = 0;
        #pragma unroll
        for (int r = 0; r < 8; r++) { s += ssum[r][tid]; k += scnt[r][tid]; }
        int masked = (g_mflag[(size_t)b * N_ + n0 + tid] == 0);
        rsum[tid] = masked ? s : 0.f;
        rcnt[tid] = masked ? k : 0;
    }
    __syncthreads();
    for (int s = 32; s > 0; s >>= 1) {
        if (tid < s) { rsum[tid] += rsum[tid + s]; rcnt[tid] += rcnt[tid + s]; }
        __syncthreads();
    }
    if (tid == 0 && rcnt[0] > 0) {
        atomicAdd(&g_sum, (double)rsum[0]);
        atomicAdd(&g_cnt, (unsigned long long)rcnt[0]);
    }
}

__global__ void cvt_w_kernel(const float* __restrict__ wq, const float* __restrict__ wk) {
    int i = (blockIdx.x * 256 + threadIdx.x) * 4;
    if (i < C_ * C_) {
        float4 a = *(const float4*)(wq + i);
        float4 b = *(const float4*)(wk + i);
        *(__nv_bfloat162*)(g_wqb + i)     = __floats2bfloat162_rn(a.x, a.y);
        *(__nv_bfloat162*)(g_wqb + i + 2) = __floats2bfloat162_rn(a.z, a.w);
        *(__nv_bfloat162*)(g_wkb + i)     = __floats2bfloat162_rn(b.x, b.y);
        *(__nv_bfloat162*)(g_wkb + i + 2) = __floats2bfloat162_rn(b.z, b.w);
    }
}

// ---------------- HMMA GEMM 128x128x64, 4 warps, 64x64 warp tile --------------
// EPI 0: dual (q/k by blockIdx.x&1). q-half gathers A rows via g_idx; early-exit
//        beyond nact. v = acc + bias[col]; bf16 store; norm2[row] += v^2.
// EPI 1: v = exp(acc * rsqrt(qn2[row]) * rsqrt(kn2[col])); bf16 store;
//        g_rsum[row] += fp32 tile-row sums (atomics).
// EPI 2: loss: d = x - gamma / rsum[row] * acc; guarded to row < nact.
template <int EPI>
__global__ void __launch_bounds__(128, 2)
mma_gemm(const __nv_bfloat16* __restrict__ Ag, const __nv_bfloat16* __restrict__ Bg,
         __nv_bfloat16* __restrict__ Cb, const float* __restrict__ bias,
         const __nv_bfloat16* __restrict__ Xb, float* __restrict__ norm2,
         const float* __restrict__ gptr,
         const __nv_bfloat16* __restrict__ Bg2, __nv_bfloat16* __restrict__ Cb2,
         const float* __restrict__ bias2, float* __restrict__ norm2b,
         int K, int lda, int ldb, int ldc,
         long long sA, long long sB, long long sC, long long sX)
{
    extern __shared__ char dsm[];
    const uint32_t dbase = (smem_u32(dsm) + 1023u) & ~1023u;

    const int tid  = threadIdx.x;
    const int lane = tid & 31;
    const int wid  = tid >> 5;           // 0..3
    const int wm   = wid & 1;            // 2 warps along M (64 rows)
    const int wn   = wid >> 1;           // 2 warps along N (64 cols)
    const int bz = blockIdx.z;
    const int m0 = blockIdx.y * TM;
    const int nact = g_nact[bz];

    int n0;
    const __nv_bfloat16* Bsel;
    __nv_bfloat16* Csel;
    const float* biasSel;
    float* normSel;
    bool gatherq = false;
    if (EPI == 0) {
        const int sel = blockIdx.x & 1;
        n0 = (blockIdx.x >> 1) * TN;
        Bsel = sel ? Bg2 : Bg;   Csel = sel ? Cb2 : Cb;
        biasSel = sel ? bias2 : bias;  normSel = sel ? norm2b : norm2;
        gatherq = (sel == 0);
        if (gatherq && m0 >= nact) return;
    } else {
        n0 = blockIdx.x * TN;
        Bsel = Bg; Csel = Cb; biasSel = bias; normSel = norm2;
        if (m0 >= nact) return;
    }

    const __nv_bfloat16* Bp = Bsel + (size_t)bz * sB + (size_t)n0 * ldb;

    // copy mapping: 128 threads, 8 rows per operand per thread, 16B each
    const int t_m = tid >> 3;            // 0..15
    const int t_k = tid & 7;             // 0..7
    uint32_t cpo[8];
    const __nv_bfloat16* arow[8];
    const __nv_bfloat16* brow[8];
    #pragma unroll
    for (int i = 0; i < 8; i++) {
        cpo[i] = SWZ((uint32_t)((t_m + 16 * i) * 128 + t_k * 16));
        int rr = m0 + t_m + 16 * i;
        int src = rr;
        if (EPI == 0 && gatherq) src = g_idx[bz * N_ + rr];
        arow[i] = Ag + (size_t)bz * sA + (size_t)src * lda;
        brow[i] = Bp + (size_t)(t_m + 16 * i) * ldb;
    }

    uint32_t a_off[4], a_sw[4];
    #pragma unroll
    for (int mt = 0; mt < 4; mt++) {
        int r = wm * 64 + mt * 16 + (lane & 15);
        a_off[mt] = (uint32_t)r * 128u;
        a_sw[mt]  = (uint32_t)(r & 7) << 4;
    }
    const uint32_t a_hi = (uint32_t)(lane >> 4) << 4;
    uint32_t b_off[4], b_sw[4];
    #pragma unroll
    for (int p = 0; p < 4; p++) {
        int r = wn * 64 + (2 * p + (lane >> 4)) * 8 + (lane & 7);
        b_off[p] = (uint32_t)r * 128u;
        b_sw[p]  = (uint32_t)(r & 7) << 4;
    }
    const uint32_t b_hi = (uint32_t)((lane >> 3) & 1) << 4;

    float acc[4][8][4] = {};
    const int KT = K / TK;

    {
        #pragma unroll
        for (int i = 0; i < 8; i++) {
            cp_async16(dbase + cpo[i],         arow[i] + t_k * 8);
            cp_async16(dbase + 16384 + cpo[i], brow[i] + t_k * 8);
        }
        cp_commit();
    }

    for (int t = 0; t < KT; t++) {
        const int s = t & 1;
        if (t + 1 < KT) {
            uint32_t sb = dbase + (uint32_t)((s ^ 1) * STAGE);
            const int kt = (t + 1) * TK;
            #pragma unroll
            for (int i = 0; i < 8; i++) {
                cp_async16(sb + cpo[i],         arow[i] + kt + t_k * 8);
                cp_async16(sb + 16384 + cpo[i], brow[i] + kt + t_k * 8);
            }
            cp_commit();
            cp_wait1();
        } else {
            cp_wait0();
        }
        __syncthreads();

        const uint32_t As = dbase + (uint32_t)(s * STAGE);
        const uint32_t Bs = As + 16384;
        #pragma unroll
        for (int ks = 0; ks < 4; ks++) {
            const uint32_t ko = (uint32_t)(ks * 32);
            uint32_t af[4][4], bf[4][4];
            #pragma unroll
            for (int mt = 0; mt < 4; mt++)
                ldsm_x4(As + a_off[mt] + ((ko + a_hi) ^ a_sw[mt]), af[mt]);
            #pragma unroll
            for (int p = 0; p < 4; p++)
                ldsm_x4(Bs + b_off[p] + ((ko + b_hi) ^ b_sw[p]), bf[p]);
            #pragma unroll
            for (int mt = 0; mt < 4; mt++)
                #pragma unroll
                for (int nt = 0; nt < 8; nt++)
                    mma_bf16(acc[mt][nt], af[mt], &bf[nt >> 1][(nt & 1) * 2]);
        }
        __syncthreads();
    }

    // ---------------- epilogue ----------------
    const int g   = lane >> 2;
    const int tig = lane & 3;
    const int rbase = m0 + wm * 64 + g;
    const int cbase = n0 + wn * 64 + tig * 2;

    if (EPI == 0) {
        __nv_bfloat16* Cbb = Csel + (size_t)bz * sC;
        #pragma unroll
        for (int mt = 0; mt < 4; mt++) {
            int r0 = rbase + mt * 16, r1 = r0 + 8;
            float s0 = 0.f, s1 = 0.f;
            #pragma unroll
            for (int nt = 0; nt < 8; nt++) {
                int c = cbase + nt * 8;
                float b0 = __ldg(biasSel + c), b1 = __ldg(biasSel + c + 1);
                float v00 = acc[mt][nt][0] + b0, v01 = acc[mt][nt][1] + b1;
                float v10 = acc[mt][nt][2] + b0, v11 = acc[mt][nt][3] + b1;
                s0 += v00 * v00 + v01 * v01;
                s1 += v10 * v10 + v11 * v11;
                *(__nv_bfloat162*)(Cbb + (size_t)r0 * ldc + c) = __floats2bfloat162_rn(v00, v01);
                *(__nv_bfloat162*)(Cbb + (size_t)r1 * ldc + c) = __floats2bfloat162_rn(v10, v11);
            }
            s0 += __shfl_xor_sync(0xffffffffu, s0, 1);
            s0 += __shfl_xor_sync(0xffffffffu, s0, 2);
            s1 += __shfl_xor_sync(0xffffffffu, s1, 1);
            s1 += __shfl_xor_sync(0xffffffffu, s1, 2);
            if (tig == 0) {
                atomicAdd(&normSel[(size_t)bz * N_ + r0], s0);
                atomicAdd(&normSel[(size_t)bz * N_ + r1], s1);
            }
        }
    } else if (EPI == 1) {
        __nv_bfloat16* Cbb = Csel + (size_t)bz * sC;
        const float* qn2 = normSel + (size_t)bz * N_;
        const float* kn2 = biasSel + (size_t)bz * N_;
        float* rsumG = g_rsum + (size_t)bz * N_;
        float sc[16];
        #pragma unroll
        for (int nt = 0; nt < 8; nt++) {
            int c = cbase + nt * 8;
            sc[nt * 2]     = rsqrtf(__ldg(kn2 + c));
            sc[nt * 2 + 1] = rsqrtf(__ldg(kn2 + c + 1));
        }
        #pragma unroll
        for (int mt = 0; mt < 4; mt++) {
            int r0 = rbase + mt * 16, r1 = r0 + 8;
            float sr0 = rsqrtf(__ldg(qn2 + r0));
            float sr1 = rsqrtf(__ldg(qn2 + r1));
            float s0 = 0.f, s1 = 0.f;
            #pragma unroll
            for (int nt = 0; nt < 8; nt++) {
                int c = cbase + nt * 8;
                float v00 = __expf(acc[mt][nt][0] * sr0 * sc[nt * 2]);
                float v01 = __expf(acc[mt][nt][1] * sr0 * sc[nt * 2 + 1]);
                float v10 = __expf(acc[mt][nt][2] * sr1 * sc[nt * 2]);
                float v11 = __expf(acc[mt][nt][3] * sr1 * sc[nt * 2 + 1]);
                s0 += v00 + v01;
                s1 += v10 + v11;
                *(__nv_bfloat162*)(Cbb + (size_t)r0 * ldc + c) = __floats2bfloat162_rn(v00, v01);
                *(__nv_bfloat162*)(Cbb + (size_t)r1 * ldc + c) = __floats2bfloat162_rn(v10, v11);
            }
            s0 += __shfl_xor_sync(0xffffffffu, s0, 1);
            s0 += __shfl_xor_sync(0xffffffffu, s0, 2);
            s1 += __shfl_xor_sync(0xffffffffu, s1, 1);
            s1 += __shfl_xor_sync(0xffffffffu, s1, 2);
            if (tig == 0) {
                atomicAdd(&rsumG[r0], s0);
                atomicAdd(&rsumG[r1], s1);
            }
        }
    } else {
        const float gm = gptr[0];
        const __nv_bfloat16* Xp = Xb + (size_t)bz * sX;
        const float* rsumG = g_rsum + (size_t)bz * N_;
        float lsum = 0.f;
        unsigned lcnt = 0;
        #pragma unroll
        for (int mt = 0; mt < 4; mt++) {
            int r0 = rbase + mt * 16, r1 = r0 + 8;
            bool ok0 = r0 < nact, ok1 = r1 < nact;
            int s0i = ok0 ? g_idx[bz * N_ + r0] : 0;
            int s1i = ok1 ? g_idx[bz * N_ + r1] : 0;
            float gi0 = ok0 ? gm / __ldg(rsumG + r0) : 0.f;
            float gi1 = ok1 ? gm / __ldg(rsumG + r1) : 0.f;
            const __nv_bfloat16* xr0 = Xp + (size_t)s0i * ldc;
            const __nv_bfloat16* xr1 = Xp + (size_t)s1i * ldc;
            #pragma unroll
            for (int nt = 0; nt < 8; nt++) {
                int c = cbase + nt * 8;
                if (ok0) {
                    __nv_bfloat162 x0 = *(const __nv_bfloat162*)(xr0 + c);
                    float d0 = __bfloat162float(x0.x) - gi0 * acc[mt][nt][0];
                    float d1 = __bfloat162float(x0.y) - gi0 * acc[mt][nt][1];
                    float r00 = d0 * d0, r01 = d1 * d1;
                    lsum += r00 + r01;
                    lcnt += (r00 != 0.f) + (r01 != 0.f);
                }
                if (ok1) {
                    __nv_bfloat162 x1 = *(const __nv_bfloat162*)(xr1 + c);
                    float d2 = __bfloat162float(x1.x) - gi1 * acc[mt][nt][2];
                    float d3 = __bfloat162float(x1.y) - gi1 * acc[mt][nt][3];
                    float r10 = d2 * d2, r11 = d3 * d3;
                    lsum += r10 + r11;
                    lcnt += (r10 != 0.f) + (r11 != 0.f);
                }
            }
        }
        #pragma unroll
        for (int o = 16; o > 0; o >>= 1) {
            lsum += __shfl_down_sync(0xffffffffu, lsum, o);
            lcnt += __shfl_down_sync(0xffffffffu, lcnt, o);
        }
        if (lane == 0) {
            atomicAdd(&g_sum, (double)lsum);
            atomicAdd(&g_cnt, (unsigned long long)lcnt);
        }
    }
}

__global__ void finalize_kernel(float* out) {
    out[0] = (float)(g_sum / (double)g_cnt);
}

// ---------------- launch --------------------------------------------------------
extern "C" void kernel_launch(void* const* d_in, const int* in_sizes, int n_in,
                              void* d_out, int out_size)
{
    const float* x     = (const float*)d_in[0];
    const float* cam   = (const float*)d_in[1];
    const float* Wq    = (const float*)d_in[2];
    const float* bq    = (const float*)d_in[3];
    const float* Wk    = (const float*)d_in[4];
    const float* bk    = (const float*)d_in[5];
    const float* gamma = (const float*)d_in[6];

    cudaFuncSetAttribute(mma_gemm<0>, cudaFuncAttributeMaxDynamicSharedMemorySize, SMEM_DYN);
    cudaFuncSetAttribute(mma_gemm<1>, cudaFuncAttributeMaxDynamicSharedMemorySize, SMEM_DYN);
    cudaFuncSetAttribute(mma_gemm<2>, cudaFuncAttributeMaxDynamicSharedMemorySize, SMEM_DYN);

    __nv_bfloat16 *pxt, *pxb, *pwq, *pwk, *pqr, *pkr, *pattb;
    float *pqn2, *pkn2;
    cudaGetSymbolAddress((void**)&pxt,   g_xt);
    cudaGetSymbolAddress((void**)&pxb,   g_xb);
    cudaGetSymbolAddress((void**)&pwq,   g_wqb);
    cudaGetSymbolAddress((void**)&pwk,   g_wkb);
    cudaGetSymbolAddress((void**)&pqr,   g_qr);
    cudaGetSymbolAddress((void**)&pkr,   g_kr);
    cudaGetSymbolAddress((void**)&pattb, g_attb);
    cudaGetSymbolAddress((void**)&pqn2,  g_qn2);
    cudaGetSymbolAddress((void**)&pkn2,  g_kn2);

    const long long sNC = (long long)N_ * C_;
    const long long sCN = (long long)C_ * N_;
    const long long sNN = (long long)N_ * N_;

    init_kernel<<<1, 32>>>();
    mask_kernel<<<(B_ * N_ + 255) / 256, 256>>>(cam);
    cvt_w_kernel<<<C_ * C_ / 1024, 256>>>(Wq, Wk);
    cvt_x_kernel<<<dim3(N_ / 64, C_ / 32, B_), dim3(32, 8)>>>(x);

    // fused q & k: q gathers active rows; k full. rownorm2; bf16 out
    mma_gemm<0><<<dim3(2 * C_ / TN, N_ / TM, B_), 128, SMEM_DYN>>>(
        pxt, pwq, pqr, bq, nullptr, pqn2, nullptr,
        pwk, pkr, bk, pkn2,
        C_, C_, C_, C_, sNC, 0LL, sNC, 0LL);
    // attb[j,m] = exp(cos-logit); bf16 out; fp32 rowsums into g_rsum
    mma_gemm<1><<<dim3(N_ / TN, N_ / TM, B_), 128, SMEM_DYN>>>(
        pqr, pkr, pattb, pkn2, nullptr, pqn2, nullptr,
        nullptr, nullptr, nullptr, nullptr,
        C_, C_, C_, N_, sNC, sNC, sNN, 0LL);
    // loss: D[j,c] = (1/rsum[j]) * sum_m attb[j,m]*xb[c,m]; compare xt[g_idx[j],c]
    mma_gemm<2><<<dim3(C_ / TN, N_ / TM, B_), 128, SMEM_DYN>>>(
        pattb, pxb, nullptr, nullptr, pxt, nullptr, gamma,
        nullptr, nullptr, nullptr, nullptr,
        N_, N_, N_, C_, sNN, sCN, 0LL, sNC);

    finalize_kernel<<<1, 1>>>((float*)d_out);
}

// round 13
// speedup vs baseline: 1.0218x; 1.0218x over previous
#include <cuda_runtime.h>
#include <cuda_bf16.h>
#include <math.h>
#include <stdint.h>

#define B_   4
#define C_   2048
#define H_   48
#define N_   2304
#define CAM_ 384

#define TM   128
#define TN   128
#define TK   64
#define STAGE 32768                 /* A: 128*128B + B: 128*128B */
#define SMEM_DYN (2*STAGE + 1024)

#define MASK_BLOCKS ((B_ * N_ + 255) / 256)     /* 36  */
#define CVTW_BLOCKS (C_ * C_ / 1024)            /* 4096 */

// ---------------- scratch (device globals) ----------------------------------
__device__ __nv_bfloat16 g_xb [B_ * C_ * N_];   // x bf16  [C,N]
__device__ __nv_bfloat16 g_xt [B_ * N_ * C_];   // x^T bf16 [N,C]
__device__ __nv_bfloat16 g_wqb[C_ * C_];
__device__ __nv_bfloat16 g_wkb[C_ * C_];
__device__ __nv_bfloat16 g_qr [B_ * N_ * C_];   // q, compacted rows
__device__ __nv_bfloat16 g_kr [B_ * N_ * C_];   // k, full rows
__device__ __nv_bfloat16 g_attb[B_ * N_ * N_];  // exp(logits), compacted rows
__device__ float g_qn2[B_ * N_];
__device__ float g_kn2[B_ * N_];
__device__ float g_rsum[B_ * N_];               // rowsum(exp), fp32
__device__ int   g_mflag[B_ * N_];
__device__ int   g_idx [B_ * N_];
__device__ int   g_nact[B_];
__device__ double g_sum;
__device__ unsigned long long g_cnt;

// ---------------- helpers -----------------------------------------------------
__device__ __forceinline__ uint32_t smem_u32(const void* p) {
    uint32_t a;
    asm("{ .reg .u64 t; cvta.to.shared.u64 t, %1; cvt.u32.u64 %0, t; }"
        : "=r"(a) : "l"(p));
    return a;
}
__device__ __forceinline__ void cp_async16(uint32_t dst, const void* src) {
    asm volatile("cp.async.cg.shared.global [%0], [%1], 16;"
                 :: "r"(dst), "l"(src) : "memory");
}
__device__ __forceinline__ void cp_commit() {
    asm volatile("cp.async.commit_group;" ::: "memory");
}
__device__ __forceinline__ void cp_wait0() {
    asm volatile("cp.async.wait_group 0;" ::: "memory");
}
__device__ __forceinline__ void cp_wait1() {
    asm volatile("cp.async.wait_group 1;" ::: "memory");
}
__device__ __forceinline__ void ldsm_x4(uint32_t addr, uint32_t* r) {
    asm volatile("ldmatrix.sync.aligned.m8n8.x4.shared.b16 {%0,%1,%2,%3}, [%4];"
        : "=r"(r[0]), "=r"(r[1]), "=r"(r[2]), "=r"(r[3]) : "r"(addr));
}
__device__ __forceinline__ void mma_bf16(float* d, const uint32_t* a, const uint32_t* b) {
    asm volatile(
        "mma.sync.aligned.m16n8k16.row.col.f32.bf16.bf16.f32 "
        "{%0,%1,%2,%3}, {%4,%5,%6,%7}, {%8,%9}, {%0,%1,%2,%3};"
        : "+f"(d[0]), "+f"(d[1]), "+f"(d[2]), "+f"(d[3])
        : "r"(a[0]), "r"(a[1]), "r"(a[2]), "r"(a[3]), "r"(b[0]), "r"(b[1]));
}
#define SWZ(o) ((o) ^ (((o) >> 3) & 0x70))

// ---------------- preamble: init + mask/compaction + W convert (one launch) ----
__global__ void preamble_kernel(const float* __restrict__ cam,
                                const float* __restrict__ wq,
                                const float* __restrict__ wk) {
    if (blockIdx.x < MASK_BLOCKS) {
        int i = blockIdx.x * 256 + threadIdx.x;
        if (i == 0) { g_sum = 0.0; g_cnt = 0ull; }
        if (i < B_) g_nact[i] = 0;
        __threadfence();            // nact zeroing visible before atomics below
        __syncthreads();
        if (i >= B_ * N_) return;
        g_qn2[i] = 0.f; g_kn2[i] = 0.f; g_rsum[i] = 0.f;
        int b = i / N_, p = i % N_;
        int oy = p / H_, ox = p % H_;
        const float step = 383.0f / 47.0f;
        float sy = (float)oy * step, sx = (float)ox * step;
        int y0 = min(max((int)floorf(sy), 0), CAM_ - 1);
        int x0 = min(max((int)floorf(sx), 0), CAM_ - 1);
        int y1 = min(y0 + 1, CAM_ - 1), x1 = min(x0 + 1, CAM_ - 1);
        float wy = sy - (float)y0, wx = sx - (float)x0;
        const float* cb = cam + (size_t)b * CAM_ * CAM_;
        float v00 = cb[y0 * CAM_ + x0]; v00 = (v00 == 255.0f) ? 0.f : v00;
        float v01 = cb[y0 * CAM_ + x1]; v01 = (v01 == 255.0f) ? 0.f : v01;
        float v10 = cb[y1 * CAM_ + x0]; v10 = (v10 == 255.0f) ? 0.f : v10;
        float v11 = cb[y1 * CAM_ + x1]; v11 = (v11 == 255.0f) ? 0.f : v11;
        float val = (1.f - wy) * ((1.f - wx) * v00 + wx * v01)
                  + wy * ((1.f - wx) * v10 + wx * v11);
        if (val > 0.f) {
            g_mflag[i] = 1;
            int slot = atomicAdd(&g_nact[b], 1);
            g_idx[b * N_ + slot] = p;
        } else {
            g_mflag[i] = 0;
        }
    } else {
        int i = ((blockIdx.x - MASK_BLOCKS) * 256 + threadIdx.x) * 4;
        if (i < C_ * C_) {
            float4 a = *(const float4*)(wq + i);
            float4 b = *(const float4*)(wk + i);
            *(__nv_bfloat162*)(g_wqb + i)     = __floats2bfloat162_rn(a.x, a.y);
            *(__nv_bfloat162*)(g_wqb + i + 2) = __floats2bfloat162_rn(a.z, a.w);
            *(__nv_bfloat162*)(g_wkb + i)     = __floats2bfloat162_rn(b.x, b.y);
            *(__nv_bfloat162*)(g_wkb + i + 2) = __floats2bfloat162_rn(b.z, b.w);
        }
    }
}

// NOTE on nact-zero visibility: block 0 zeroes g_nact before any atomicAdd in
// that same grid can run? Not guaranteed across blocks. Instead zero nact in a
// dedicated tiny kernel before preamble to stay safe.
__global__ void zero_nact_kernel() {
    if (threadIdx.x == 0) { g_sum = 0.0; g_cnt = 0ull; }
    if (threadIdx.x < B_) g_nact[threadIdx.x] = 0;
}

// x fp32 [C,N] -> g_xb bf16 [C,N], g_xt bf16 [N,C]; masked-row loss, atomic-free
__global__ void cvt_x_kernel(const float* __restrict__ x) {
    __shared__ float tile[64][33];
    __shared__ float ssum[8][64];
    __shared__ int   scnt[8][64];
    __shared__ float rsum[64];
    __shared__ int   rcnt[64];
    const int b = blockIdx.z;
    const int n0 = blockIdx.x * 64, c0 = blockIdx.y * 32;
    const int tx = threadIdx.x, ty = threadIdx.y;   // 32 x 8
    const int tid = ty * 32 + tx;
    const float* xp = x + (size_t)b * C_ * N_;
    __nv_bfloat16* xbp = g_xb + (size_t)b * C_ * N_;
    __nv_bfloat16* xtp = g_xt + (size_t)b * N_ * C_;

    float s0 = 0.f, s1 = 0.f;
    int   k0 = 0,   k1 = 0;
    #pragma unroll
    for (int r = 0; r < 4; r++) {
        int c = c0 + ty + r * 8;
        float2 v = *(const float2*)(xp + (size_t)c * N_ + n0 + tx * 2);
        tile[tx * 2][ty + r * 8]     = v.x;
        tile[tx * 2 + 1][ty + r * 8] = v.y;
        *(__nv_bfloat162*)(xbp + (size_t)c * N_ + n0 + tx * 2) =
            __floats2bfloat162_rn(v.x, v.y);
        s0 += v.x * v.x; k0 += (v.x != 0.f);
        s1 += v.y * v.y; k1 += (v.y != 0.f);
    }
    ssum[ty][tx * 2] = s0; ssum[ty][tx * 2 + 1] = s1;
    scnt[ty][tx * 2] = k0; scnt[ty][tx * 2 + 1] = k1;
    __syncthreads();

    const int half = tx >> 4, cp2 = (tx & 15) * 2;
    #pragma unroll
    for (int r = 0; r < 4; r++) {
        int nl = ty * 2 + half + r * 16;
        *(__nv_bfloat162*)(xtp + (size_t)(n0 + nl) * C_ + c0 + cp2) =
            __floats2bfloat162_rn(tile[nl][cp2], tile[nl][cp2 + 1]);
    }
    if (tid < 64) {
        float s = 0.f; int k = 0;
        #pragma unroll
        for (int r = 0; r < 8; r++) { s += ssum[r][tid]; k += scnt[r][tid]; }
        int masked = (g_mflag[(size_t)b * N_ + n0 + tid] == 0);
        rsum[tid] = masked ? s : 0.f;
        rcnt[tid] = masked ? k : 0;
    }
    __syncthreads();
    for (int s = 32; s > 0; s >>= 1) {
        if (tid < s) { rsum[tid] += rsum[tid + s]; rcnt[tid] += rcnt[tid + s]; }
        __syncthreads();
    }
    if (tid == 0 && rcnt[0] > 0) {
        atomicAdd(&g_sum, (double)rsum[0]);
        atomicAdd(&g_cnt, (unsigned long long)rcnt[0]);
    }
}

// ---------------- HMMA GEMM 128x128x64 (R11 mainloop, 8 warps 64x32) ----------
// EPI 0: dual (q/k by blockIdx.x&1). q-half gathers A rows via g_idx; early-exit
//        beyond nact. v = acc + bias[col]; bf16 store; norm2[row] += v^2.
// EPI 1: v = exp(acc * rsqrt(qn2[row]) * rsqrt(kn2[col])); bf16 store;
//        g_rsum[row] += fp32 tile-row sums (atomics).
// EPI 2: loss: d = x - gamma / rsum[row] * acc; guarded to row < nact.
template <int EPI>
__global__ void __launch_bounds__(256, 2)
mma_gemm(const __nv_bfloat16* __restrict__ Ag, const __nv_bfloat16* __restrict__ Bg,
         __nv_bfloat16* __restrict__ Cb, const float* __restrict__ bias,
         const __nv_bfloat16* __restrict__ Xb, float* __restrict__ norm2,
         const float* __restrict__ gptr,
         const __nv_bfloat16* __restrict__ Bg2, __nv_bfloat16* __restrict__ Cb2,
         const float* __restrict__ bias2, float* __restrict__ norm2b,
         int K, int lda, int ldb, int ldc,
         long long sA, long long sB, long long sC, long long sX)
{
    extern __shared__ char dsm[];
    const uint32_t dbase = (smem_u32(dsm) + 1023u) & ~1023u;

    const int tid  = threadIdx.x;
    const int lane = tid & 31;
    const int wid  = tid >> 5;
    const int wm   = wid & 1;
    const int wn   = wid >> 1;
    const int bz = blockIdx.z;
    const int m0 = blockIdx.y * TM;
    const int nact = g_nact[bz];

    int n0;
    const __nv_bfloat16* Bsel;
    __nv_bfloat16* Csel;
    const float* biasSel;
    float* normSel;
    bool gatherq = false;
    if (EPI == 0) {
        const int sel = blockIdx.x & 1;
        n0 = (blockIdx.x >> 1) * TN;
        Bsel = sel ? Bg2 : Bg;   Csel = sel ? Cb2 : Cb;
        biasSel = sel ? bias2 : bias;  normSel = sel ? norm2b : norm2;
        gatherq = (sel == 0);
        if (gatherq && m0 >= nact) return;
    } else {
        n0 = blockIdx.x * TN;
        Bsel = Bg; Csel = Cb; biasSel = bias; normSel = norm2;
        if (m0 >= nact) return;
    }

    const __nv_bfloat16* Bp = Bsel + (size_t)bz * sB + (size_t)n0 * ldb;

    const int t_m = tid >> 3;
    const int t_k = tid & 7;
    uint32_t cpo[4];
    const __nv_bfloat16* arow[4];
    const __nv_bfloat16* brow[4];
    #pragma unroll
    for (int i = 0; i < 4; i++) {
        cpo[i] = SWZ((uint32_t)((t_m + 32 * i) * 128 + t_k * 16));
        int rr = m0 + t_m + 32 * i;
        int src = rr;
        if (EPI == 0 && gatherq) src = g_idx[bz * N_ + rr];
        arow[i] = Ag + (size_t)bz * sA + (size_t)src * lda;
        brow[i] = Bp + (size_t)(t_m + 32 * i) * ldb;
    }

    uint32_t a_off[4], a_sw[4];
    #pragma unroll
    for (int mt = 0; mt < 4; mt++) {
        int r = wm * 64 + mt * 16 + (lane & 15);
        a_off[mt] = (uint32_t)r * 128u;
        a_sw[mt]  = (uint32_t)(r & 7) << 4;
    }
    const uint32_t a_hi = (uint32_t)(lane >> 4) << 4;
    uint32_t b_off[2], b_sw[2];
    #pragma unroll
    for (int p = 0; p < 2; p++) {
        int r = wn * 32 + (2 * p + (lane >> 4)) * 8 + (lane & 7);
        b_off[p] = (uint32_t)r * 128u;
        b_sw[p]  = (uint32_t)(r & 7) << 4;
    }
    const uint32_t b_hi = (uint32_t)((lane >> 3) & 1) << 4;

    float acc[4][4][4] = {};
    const int KT = K / TK;

    {
        #pragma unroll
        for (int i = 0; i < 4; i++) {
            cp_async16(dbase + cpo[i],         arow[i] + t_k * 8);
            cp_async16(dbase + 16384 + cpo[i], brow[i] + t_k * 8);
        }
        cp_commit();
    }

    for (int t = 0; t < KT; t++) {
        const int s = t & 1;
        if (t + 1 < KT) {
            uint32_t sb = dbase + (uint32_t)((s ^ 1) * STAGE);
            const int kt = (t + 1) * TK;
            #pragma unroll
            for (int i = 0; i < 4; i++) {
                cp_async16(sb + cpo[i],         arow[i] + kt + t_k * 8);
                cp_async16(sb + 16384 + cpo[i], brow[i] + kt + t_k * 8);
            }
            cp_commit();
            cp_wait1();
        } else {
            cp_wait0();
        }
        __syncthreads();

        const uint32_t As = dbase + (uint32_t)(s * STAGE);
        const uint32_t Bs = As + 16384;
        #pragma unroll
        for (int ks = 0; ks < 4; ks++) {
            const uint32_t ko = (uint32_t)(ks * 32);
            uint32_t af[4][4], bf2[2][4];
            #pragma unroll
            for (int mt = 0; mt < 4; mt++)
                ldsm_x4(As + a_off[mt] + ((ko + a_hi) ^ a_sw[mt]), af[mt]);
            #pragma unroll
            for (int p = 0; p < 2; p++)
                ldsm_x4(Bs + b_off[p] + ((ko + b_hi) ^ b_sw[p]), bf2[p]);
            #pragma unroll
            for (int mt = 0; mt < 4; mt++)
                #pragma unroll
                for (int nt = 0; nt < 4; nt++)
                    mma_bf16(acc[mt][nt], af[mt], &bf2[nt >> 1][(nt & 1) * 2]);
        }
        __syncthreads();
    }

    // ---------------- epilogue ----------------
    const int g   = lane >> 2;
    const int tig = lane & 3;
    const int rbase = m0 + wm * 64 + g;
    const int cbase = n0 + wn * 32 + tig * 2;

    if (EPI == 0) {
        __nv_bfloat16* Cbb = Csel + (size_t)bz * sC;
        #pragma unroll
        for (int mt = 0; mt < 4; mt++) {
            int r0 = rbase + mt * 16, r1 = r0 + 8;
            float s0 = 0.f, s1 = 0.f;
            #pragma unroll
            for (int nt = 0; nt < 4; nt++) {
                int c = cbase + nt * 8;
                float b0 = __ldg(biasSel + c), b1 = __ldg(biasSel + c + 1);
                float v00 = acc[mt][nt][0] + b0, v01 = acc[mt][nt][1] + b1;
                float v10 = acc[mt][nt][2] + b0, v11 = acc[mt][nt][3] + b1;
                s0 += v00 * v00 + v01 * v01;
                s1 += v10 * v10 + v11 * v11;
                *(__nv_bfloat162*)(Cbb + (size_t)r0 * ldc + c) = __floats2bfloat162_rn(v00, v01);
                *(__nv_bfloat162*)(Cbb + (size_t)r1 * ldc + c) = __floats2bfloat162_rn(v10, v11);
            }
            s0 += __shfl_xor_sync(0xffffffffu, s0, 1);
            s0 += __shfl_xor_sync(0xffffffffu, s0, 2);
            s1 += __shfl_xor_sync(0xffffffffu, s1, 1);
            s1 += __shfl_xor_sync(0xffffffffu, s1, 2);
            if (tig == 0) {
                atomicAdd(&normSel[(size_t)bz * N_ + r0], s0);
                atomicAdd(&normSel[(size_t)bz * N_ + r1], s1);
            }
        }
    } else if (EPI == 1) {
        __nv_bfloat16* Cbb = Csel + (size_t)bz * sC;
        const float* qn2 = normSel + (size_t)bz * N_;
        const float* kn2 = biasSel + (size_t)bz * N_;
        float* rsumG = g_rsum + (size_t)bz * N_;
        float sc[8];
        #pragma unroll
        for (int nt = 0; nt < 4; nt++) {
            int c = cbase + nt * 8;
            sc[nt * 2]     = rsqrtf(__ldg(kn2 + c));
            sc[nt * 2 + 1] = rsqrtf(__ldg(kn2 + c + 1));
        }
        #pragma unroll
        for (int mt = 0; mt < 4; mt++) {
            int r0 = rbase + mt * 16, r1 = r0 + 8;
            float sr0 = rsqrtf(__ldg(qn2 + r0));
            float sr1 = rsqrtf(__ldg(qn2 + r1));
            float s0 = 0.f, s1 = 0.f;
            #pragma unroll
            for (int nt = 0; nt < 4; nt++) {
                int c = cbase + nt * 8;
                float v00 = __expf(acc[mt][nt][0] * sr0 * sc[nt * 2]);
                float v01 = __expf(acc[mt][nt][1] * sr0 * sc[nt * 2 + 1]);
                float v10 = __expf(acc[mt][nt][2] * sr1 * sc[nt * 2]);
                float v11 = __expf(acc[mt][nt][3] * sr1 * sc[nt * 2 + 1]);
                s0 += v00 + v01;
                s1 += v10 + v11;
                *(__nv_bfloat162*)(Cbb + (size_t)r0 * ldc + c) = __floats2bfloat162_rn(v00, v01);
                *(__nv_bfloat162*)(Cbb + (size_t)r1 * ldc + c) = __floats2bfloat162_rn(v10, v11);
            }
            s0 += __shfl_xor_sync(0xffffffffu, s0, 1);
            s0 += __shfl_xor_sync(0xffffffffu, s0, 2);
            s1 += __shfl_xor_sync(0xffffffffu, s1, 1);
            s1 += __shfl_xor_sync(0xffffffffu, s1, 2);
            if (tig == 0) {
                atomicAdd(&rsumG[r0], s0);
                atomicAdd(&rsumG[r1], s1);
            }
        }
    } else {
        const float gm = gptr[0];
        const __nv_bfloat16* Xp = Xb + (size_t)bz * sX;
        const float* rsumG = g_rsum + (size_t)bz * N_;
        float lsum = 0.f;
        unsigned lcnt = 0;
        #pragma unroll
        for (int mt = 0; mt < 4; mt++) {
            int r0 = rbase + mt * 16, r1 = r0 + 8;
            bool ok0 = r0 < nact, ok1 = r1 < nact;
            int s0i = ok0 ? g_idx[bz * N_ + r0] : 0;
            int s1i = ok1 ? g_idx[bz * N_ + r1] : 0;
            float gi0 = ok0 ? gm / __ldg(rsumG + r0) : 0.f;
            float gi1 = ok1 ? gm / __ldg(rsumG + r1) : 0.f;
            const __nv_bfloat16* xr0 = Xp + (size_t)s0i * ldc;
            const __nv_bfloat16* xr1 = Xp + (size_t)s1i * ldc;
            #pragma unroll
            for (int nt = 0; nt < 4; nt++) {
                int c = cbase + nt * 8;
                if (ok0) {
                    __nv_bfloat162 x0 = *(const __nv_bfloat162*)(xr0 + c);
                    float d0 = __bfloat162float(x0.x) - gi0 * acc[mt][nt][0];
                    float d1 = __bfloat162float(x0.y) - gi0 * acc[mt][nt][1];
                    float r00 = d0 * d0, r01 = d1 * d1;
                    lsum += r00 + r01;
                    lcnt += (r00 != 0.f) + (r01 != 0.f);
                }
                if (ok1) {
                    __nv_bfloat162 x1 = *(const __nv_bfloat162*)(xr1 + c);
                    float d2 = __bfloat162float(x1.x) - gi1 * acc[mt][nt][2];
                    float d3 = __bfloat162float(x1.y) - gi1 * acc[mt][nt][3];
                    float r10 = d2 * d2, r11 = d3 * d3;
                    lsum += r10 + r11;
                    lcnt += (r10 != 0.f) + (r11 != 0.f);
                }
            }
        }
        #pragma unroll
        for (int o = 16; o > 0; o >>= 1) {
            lsum += __shfl_down_sync(0xffffffffu, lsum, o);
            lcnt += __shfl_down_sync(0xffffffffu, lcnt, o);
        }
        if (lane == 0) {
            atomicAdd(&g_sum, (double)lsum);
            atomicAdd(&g_cnt, (unsigned long long)lcnt);
        }
    }
}

__global__ void finalize_kernel(float* out) {
    out[0] = (float)(g_sum / (double)g_cnt);
}

// ---------------- launch --------------------------------------------------------
extern "C" void kernel_launch(void* const* d_in, const int* in_sizes, int n_in,
                              void* d_out, int out_size)
{
    const float* x     = (const float*)d_in[0];
    const float* cam   = (const float*)d_in[1];
    const float* Wq    = (const float*)d_in[2];
    const float* bq    = (const float*)d_in[3];
    const float* Wk    = (const float*)d_in[4];
    const float* bk    = (const float*)d_in[5];
    const float* gamma = (const float*)d_in[6];

    cudaFuncSetAttribute(mma_gemm<0>, cudaFuncAttributeMaxDynamicSharedMemorySize, SMEM_DYN);
    cudaFuncSetAttribute(mma_gemm<1>, cudaFuncAttributeMaxDynamicSharedMemorySize, SMEM_DYN);
    cudaFuncSetAttribute(mma_gemm<2>, cudaFuncAttributeMaxDynamicSharedMemorySize, SMEM_DYN);

    __nv_bfloat16 *pxt, *pxb, *pwq, *pwk, *pqr, *pkr, *pattb;
    float *pqn2, *pkn2;
    cudaGetSymbolAddress((void**)&pxt,   g_xt);
    cudaGetSymbolAddress((void**)&pxb,   g_xb);
    cudaGetSymbolAddress((void**)&pwq,   g_wqb);
    cudaGetSymbolAddress((void**)&pwk,   g_wkb);
    cudaGetSymbolAddress((void**)&pqr,   g_qr);
    cudaGetSymbolAddress((void**)&pkr,   g_kr);
    cudaGetSymbolAddress((void**)&pattb, g_attb);
    cudaGetSymbolAddress((void**)&pqn2,  g_qn2);
    cudaGetSymbolAddress((void**)&pkn2,  g_kn2);

    const long long sNC = (long long)N_ * C_;
    const long long sCN = (long long)C_ * N_;
    const long long sNN = (long long)N_ * N_;

    zero_nact_kernel<<<1, 32>>>();
    preamble_kernel<<<MASK_BLOCKS + CVTW_BLOCKS, 256>>>(cam, Wq, Wk);
    cvt_x_kernel<<<dim3(N_ / 64, C_ / 32, B_), dim3(32, 8)>>>(x);

    // fused q & k: q gathers active rows; k full. rownorm2; bf16 out
    mma_gemm<0><<<dim3(2 * C_ / TN, N_ / TM, B_), 256, SMEM_DYN>>>(
        pxt, pwq, pqr, bq, nullptr, pqn2, nullptr,
        pwk, pkr, bk, pkn2,
        C_, C_, C_, C_, sNC, 0LL, sNC, 0LL);
    // attb[j,m] = exp(cos-logit); bf16 out; fp32 rowsums into g_rsum
    mma_gemm<1><<<dim3(N_ / TN, N_ / TM, B_), 256, SMEM_DYN>>>(
        pqr, pkr, pattb, pkn2, nullptr, pqn2, nullptr,
        nullptr, nullptr, nullptr, nullptr,
        C_, C_, C_, N_, sNC, sNC, sNN, 0LL);
    // loss: D[j,c] = (1/rsum[j]) * sum_m attb[j,m]*xb[c,m]; compare xt[g_idx[j],c]
    mma_gemm<2><<<dim3(C_ / TN, N_ / TM, B_), 256, SMEM_DYN>>>(
        pattb, pxb, nullptr, nullptr, pxt, nullptr, gamma,
        nullptr, nullptr, nullptr, nullptr,
        N_, N_, N_, C_, sNN, sCN, 0LL, sNC);

    finalize_kernel<<<1, 1>>>((float*)d_out);
}

// round 14
// speedup vs baseline: 1.0341x; 1.0120x over previous
#include <cuda_runtime.h>
#include <cuda_bf16.h>
#include <math.h>
#include <stdint.h>

#define B_   4
#define C_   2048
#define H_   48
#define N_   2304
#define CAM_ 384

#define TM   128
#define TN   128
#define TK   64
#define STAGE 32768                 /* A: 128*128B + B: 128*128B */
#define NSTAGE 3
#define SMEM_DYN (NSTAGE*STAGE + 1024)

#define MASK_BLOCKS ((B_ * N_ + 255) / 256)     /* 36  */
#define CVTW_BLOCKS (C_ * C_ / 1024)            /* 4096 */

// ---------------- scratch (device globals) ----------------------------------
__device__ __nv_bfloat16 g_xb [B_ * C_ * N_];   // x bf16  [C,N]
__device__ __nv_bfloat16 g_xt [B_ * N_ * C_];   // x^T bf16 [N,C]
__device__ __nv_bfloat16 g_wqb[C_ * C_];
__device__ __nv_bfloat16 g_wkb[C_ * C_];
__device__ __nv_bfloat16 g_qr [B_ * N_ * C_];   // q, compacted rows
__device__ __nv_bfloat16 g_kr [B_ * N_ * C_];   // k, full rows
__device__ __nv_bfloat16 g_attb[B_ * N_ * N_];  // exp(logits), compacted rows
__device__ float g_qn2[B_ * N_];
__device__ float g_kn2[B_ * N_];
__device__ float g_rsum[B_ * N_];               // rowsum(exp), fp32
__device__ int   g_mflag[B_ * N_];
__device__ int   g_idx [B_ * N_];
__device__ int   g_nact[B_];
__device__ double g_sum;
__device__ unsigned long long g_cnt;

// ---------------- helpers -----------------------------------------------------
__device__ __forceinline__ uint32_t smem_u32(const void* p) {
    uint32_t a;
    asm("{ .reg .u64 t; cvta.to.shared.u64 t, %1; cvt.u32.u64 %0, t; }"
        : "=r"(a) : "l"(p));
    return a;
}
__device__ __forceinline__ void cp_async16(uint32_t dst, const void* src) {
    asm volatile("cp.async.cg.shared.global [%0], [%1], 16;"
                 :: "r"(dst), "l"(src) : "memory");
}
__device__ __forceinline__ void cp_commit() {
    asm volatile("cp.async.commit_group;" ::: "memory");
}
__device__ __forceinline__ void cp_wait0() {
    asm volatile("cp.async.wait_group 0;" ::: "memory");
}
__device__ __forceinline__ void cp_wait1() {
    asm volatile("cp.async.wait_group 1;" ::: "memory");
}
__device__ __forceinline__ void ldsm_x4(uint32_t addr, uint32_t* r) {
    asm volatile("ldmatrix.sync.aligned.m8n8.x4.shared.b16 {%0,%1,%2,%3}, [%4];"
        : "=r"(r[0]), "=r"(r[1]), "=r"(r[2]), "=r"(r[3]) : "r"(addr));
}
__device__ __forceinline__ void mma_bf16(float* d, const uint32_t* a, const uint32_t* b) {
    asm volatile(
        "mma.sync.aligned.m16n8k16.row.col.f32.bf16.bf16.f32 "
        "{%0,%1,%2,%3}, {%4,%5,%6,%7}, {%8,%9}, {%0,%1,%2,%3};"
        : "+f"(d[0]), "+f"(d[1]), "+f"(d[2]), "+f"(d[3])
        : "r"(a[0]), "r"(a[1]), "r"(a[2]), "r"(a[3]), "r"(b[0]), "r"(b[1]));
}
#define SWZ(o) ((o) ^ (((o) >> 3) & 0x70))

// ---------------- preamble: mask/compaction + W convert (one launch) -----------
__global__ void preamble_kernel(const float* __restrict__ cam,
                                const float* __restrict__ wq,
                                const float* __restrict__ wk) {
    if (blockIdx.x < MASK_BLOCKS) {
        int i = blockIdx.x * 256 + threadIdx.x;
        if (i >= B_ * N_) return;
        g_qn2[i] = 0.f; g_kn2[i] = 0.f; g_rsum[i] = 0.f;
        int b = i / N_, p = i % N_;
        int oy = p / H_, ox = p % H_;
        const float step = 383.0f / 47.0f;
        float sy = (float)oy * step, sx = (float)ox * step;
        int y0 = min(max((int)floorf(sy), 0), CAM_ - 1);
        int x0 = min(max((int)floorf(sx), 0), CAM_ - 1);
        int y1 = min(y0 + 1, CAM_ - 1), x1 = min(x0 + 1, CAM_ - 1);
        float wy = sy - (float)y0, wx = sx - (float)x0;
        const float* cb = cam + (size_t)b * CAM_ * CAM_;
        float v00 = cb[y0 * CAM_ + x0]; v00 = (v00 == 255.0f) ? 0.f : v00;
        float v01 = cb[y0 * CAM_ + x1]; v01 = (v01 == 255.0f) ? 0.f : v01;
        float v10 = cb[y1 * CAM_ + x0]; v10 = (v10 == 255.0f) ? 0.f : v10;
        float v11 = cb[y1 * CAM_ + x1]; v11 = (v11 == 255.0f) ? 0.f : v11;
        float val = (1.f - wy) * ((1.f - wx) * v00 + wx * v01)
                  + wy * ((1.f - wx) * v10 + wx * v11);
        if (val > 0.f) {
            g_mflag[i] = 1;
            int slot = atomicAdd(&g_nact[b], 1);
            g_idx[b * N_ + slot] = p;
        } else {
            g_mflag[i] = 0;
        }
    } else {
        int i = ((blockIdx.x - MASK_BLOCKS) * 256 + threadIdx.x) * 4;
        if (i < C_ * C_) {
            float4 a = *(const float4*)(wq + i);
            float4 b = *(const float4*)(wk + i);
            *(__nv_bfloat162*)(g_wqb + i)     = __floats2bfloat162_rn(a.x, a.y);
            *(__nv_bfloat162*)(g_wqb + i + 2) = __floats2bfloat162_rn(a.z, a.w);
            *(__nv_bfloat162*)(g_wkb + i)     = __floats2bfloat162_rn(b.x, b.y);
            *(__nv_bfloat162*)(g_wkb + i + 2) = __floats2bfloat162_rn(b.z, b.w);
        }
    }
}

__global__ void zero_nact_kernel() {
    if (threadIdx.x == 0) { g_sum = 0.0; g_cnt = 0ull; }
    if (threadIdx.x < B_) g_nact[threadIdx.x] = 0;
}

// x fp32 [C,N] -> g_xb bf16 [C,N], g_xt bf16 [N,C]; masked-row loss, atomic-free
__global__ void cvt_x_kernel(const float* __restrict__ x) {
    __shared__ float tile[64][33];
    __shared__ float ssum[8][64];
    __shared__ int   scnt[8][64];
    __shared__ float rsum[64];
    __shared__ int   rcnt[64];
    const int b = blockIdx.z;
    const int n0 = blockIdx.x * 64, c0 = blockIdx.y * 32;
    const int tx = threadIdx.x, ty = threadIdx.y;   // 32 x 8
    const int tid = ty * 32 + tx;
    const float* xp = x + (size_t)b * C_ * N_;
    __nv_bfloat16* xbp = g_xb + (size_t)b * C_ * N_;
    __nv_bfloat16* xtp = g_xt + (size_t)b * N_ * C_;

    float s0 = 0.f, s1 = 0.f;
    int   k0 = 0,   k1 = 0;
    #pragma unroll
    for (int r = 0; r < 4; r++) {
        int c = c0 + ty + r * 8;
        float2 v = *(const float2*)(xp + (size_t)c * N_ + n0 + tx * 2);
        tile[tx * 2][ty + r * 8]     = v.x;
        tile[tx * 2 + 1][ty + r * 8] = v.y;
        *(__nv_bfloat162*)(xbp + (size_t)c * N_ + n0 + tx * 2) =
            __floats2bfloat162_rn(v.x, v.y);
        s0 += v.x * v.x; k0 += (v.x != 0.f);
        s1 += v.y * v.y; k1 += (v.y != 0.f);
    }
    ssum[ty][tx * 2] = s0; ssum[ty][tx * 2 + 1] = s1;
    scnt[ty][tx * 2] = k0; scnt[ty][tx * 2 + 1] = k1;
    __syncthreads();

    const int half = tx >> 4, cp2 = (tx & 15) * 2;
    #pragma unroll
    for (int r = 0; r < 4; r++) {
        int nl = ty * 2 + half + r * 16;
        *(__nv_bfloat162*)(xtp + (size_t)(n0 + nl) * C_ + c0 + cp2) =
            __floats2bfloat162_rn(tile[nl][cp2], tile[nl][cp2 + 1]);
    }
    if (tid < 64) {
        float s = 0.f; int k = 0;
        #pragma unroll
        for (int r = 0; r < 8; r++) { s += ssum[r][tid]; k += scnt[r][tid]; }
        int masked = (g_mflag[(size_t)b * N_ + n0 + tid] == 0);
        rsum[tid] = masked ? s : 0.f;
        rcnt[tid] = masked ? k : 0;
    }
    __syncthreads();
    for (int s = 32; s > 0; s >>= 1) {
        if (tid < s) { rsum[tid] += rsum[tid + s]; rcnt[tid] += rcnt[tid + s]; }
        __syncthreads();
    }
    if (tid == 0 && rcnt[0] > 0) {
        atomicAdd(&g_sum, (double)rsum[0]);
        atomicAdd(&g_cnt, (unsigned long long)rcnt[0]);
    }
}

// ---------------- HMMA GEMM 128x128x64, 3-stage single-sync mainloop -----------
// EPI 0: dual (q/k by blockIdx.x&1). q-half gathers A rows via g_idx; early-exit
//        beyond nact. v = acc + bias[col]; bf16 store; norm2[row] += v^2.
// EPI 1: v = exp(acc * rsqrt(qn2[row]) * rsqrt(kn2[col])); bf16 store;
//        g_rsum[row] += fp32 tile-row sums (atomics).
// EPI 2: loss: d = x - gamma / rsum[row] * acc; guarded to row < nact.
template <int EPI>
__global__ void __launch_bounds__(256, 2)
mma_gemm(const __nv_bfloat16* __restrict__ Ag, const __nv_bfloat16* __restrict__ Bg,
         __nv_bfloat16* __restrict__ Cb, const float* __restrict__ bias,
         const __nv_bfloat16* __restrict__ Xb, float* __restrict__ norm2,
         const float* __restrict__ gptr,
         const __nv_bfloat16* __restrict__ Bg2, __nv_bfloat16* __restrict__ Cb2,
         const float* __restrict__ bias2, float* __restrict__ norm2b,
         int K, int lda, int ldb, int ldc,
         long long sA, long long sB, long long sC, long long sX)
{
    extern __shared__ char dsm[];
    const uint32_t dbase = (smem_u32(dsm) + 1023u) & ~1023u;

    const int tid  = threadIdx.x;
    const int lane = tid & 31;
    const int wid  = tid >> 5;
    const int wm   = wid & 1;
    const int wn   = wid >> 1;
    const int bz = blockIdx.z;
    const int m0 = blockIdx.y * TM;
    const int nact = g_nact[bz];

    int n0;
    const __nv_bfloat16* Bsel;
    __nv_bfloat16* Csel;
    const float* biasSel;
    float* normSel;
    bool gatherq = false;
    if (EPI == 0) {
        const int sel = blockIdx.x & 1;
        n0 = (blockIdx.x >> 1) * TN;
        Bsel = sel ? Bg2 : Bg;   Csel = sel ? Cb2 : Cb;
        biasSel = sel ? bias2 : bias;  normSel = sel ? norm2b : norm2;
        gatherq = (sel == 0);
        if (gatherq && m0 >= nact) return;
    } else {
        n0 = blockIdx.x * TN;
        Bsel = Bg; Csel = Cb; biasSel = bias; normSel = norm2;
        if (m0 >= nact) return;
    }

    const __nv_bfloat16* Bp = Bsel + (size_t)bz * sB + (size_t)n0 * ldb;

    const int t_m = tid >> 3;
    const int t_k = tid & 7;
    uint32_t cpo[4];
    const __nv_bfloat16* arow[4];
    const __nv_bfloat16* brow[4];
    #pragma unroll
    for (int i = 0; i < 4; i++) {
        cpo[i] = SWZ((uint32_t)((t_m + 32 * i) * 128 + t_k * 16));
        int rr = m0 + t_m + 32 * i;
        int src = rr;
        if (EPI == 0 && gatherq) src = g_idx[bz * N_ + rr];
        arow[i] = Ag + (size_t)bz * sA + (size_t)src * lda;
        brow[i] = Bp + (size_t)(t_m + 32 * i) * ldb;
    }

    uint32_t a_off[4], a_sw[4];
    #pragma unroll
    for (int mt = 0; mt < 4; mt++) {
        int r = wm * 64 + mt * 16 + (lane & 15);
        a_off[mt] = (uint32_t)r * 128u;
        a_sw[mt]  = (uint32_t)(r & 7) << 4;
    }
    const uint32_t a_hi = (uint32_t)(lane >> 4) << 4;
    uint32_t b_off[2], b_sw[2];
    #pragma unroll
    for (int p = 0; p < 2; p++) {
        int r = wn * 32 + (2 * p + (lane >> 4)) * 8 + (lane & 7);
        b_off[p] = (uint32_t)r * 128u;
        b_sw[p]  = (uint32_t)(r & 7) << 4;
    }
    const uint32_t b_hi = (uint32_t)((lane >> 3) & 1) << 4;

    float acc[4][4][4] = {};
    const int KT = K / TK;

    auto issue = [&](int t, int s) {
        uint32_t sb = dbase + (uint32_t)(s * STAGE);
        const int kt = t * TK;
        #pragma unroll
        for (int i = 0; i < 4; i++) {
            cp_async16(sb + cpo[i],         arow[i] + kt + t_k * 8);
            cp_async16(sb + 16384 + cpo[i], brow[i] + kt + t_k * 8);
        }
        cp_commit();
    };

    issue(0, 0);
    issue(1, 1);

    int s_cmp = 0, s_iss = 2;
    for (int t = 0; t < KT; t++) {
        if (t + 1 < KT) cp_wait1();   // group t complete (t, t+1 outstanding)
        else            cp_wait0();
        __syncthreads();              // all warps done reading stage being reused
        if (t + 2 < KT) {
            issue(t + 2, s_iss);
            s_iss = (s_iss == 2) ? 0 : s_iss + 1;
        }

        const uint32_t As = dbase + (uint32_t)(s_cmp * STAGE);
        const uint32_t Bs = As + 16384;
        s_cmp = (s_cmp == 2) ? 0 : s_cmp + 1;
        #pragma unroll
        for (int ks = 0; ks < 4; ks++) {
            const uint32_t ko = (uint32_t)(ks * 32);
            uint32_t af[4][4], bf2[2][4];
            #pragma unroll
            for (int mt = 0; mt < 4; mt++)
                ldsm_x4(As + a_off[mt] + ((ko + a_hi) ^ a_sw[mt]), af[mt]);
            #pragma unroll
            for (int p = 0; p < 2; p++)
                ldsm_x4(Bs + b_off[p] + ((ko + b_hi) ^ b_sw[p]), bf2[p]);
            #pragma unroll
            for (int mt = 0; mt < 4; mt++)
                #pragma unroll
                for (int nt = 0; nt < 4; nt++)
                    mma_bf16(acc[mt][nt], af[mt], &bf2[nt >> 1][(nt & 1) * 2]);
        }
    }

    // ---------------- epilogue ----------------
    const int g   = lane >> 2;
    const int tig = lane & 3;
    const int rbase = m0 + wm * 64 + g;
    const int cbase = n0 + wn * 32 + tig * 2;

    if (EPI == 0) {
        __nv_bfloat16* Cbb = Csel + (size_t)bz * sC;
        #pragma unroll
        for (int mt = 0; mt < 4; mt++) {
            int r0 = rbase + mt * 16, r1 = r0 + 8;
            float s0 = 0.f, s1 = 0.f;
            #pragma unroll
            for (int nt = 0; nt < 4; nt++) {
                int c = cbase + nt * 8;
                float b0 = __ldg(biasSel + c), b1 = __ldg(biasSel + c + 1);
                float v00 = acc[mt][nt][0] + b0, v01 = acc[mt][nt][1] + b1;
                float v10 = acc[mt][nt][2] + b0, v11 = acc[mt][nt][3] + b1;
                s0 += v00 * v00 + v01 * v01;
                s1 += v10 * v10 + v11 * v11;
                *(__nv_bfloat162*)(Cbb + (size_t)r0 * ldc + c) = __floats2bfloat162_rn(v00, v01);
                *(__nv_bfloat162*)(Cbb + (size_t)r1 * ldc + c) = __floats2bfloat162_rn(v10, v11);
            }
            s0 += __shfl_xor_sync(0xffffffffu, s0, 1);
            s0 += __shfl_xor_sync(0xffffffffu, s0, 2);
            s1 += __shfl_xor_sync(0xffffffffu, s1, 1);
            s1 += __shfl_xor_sync(0xffffffffu, s1, 2);
            if (tig == 0) {
                atomicAdd(&normSel[(size_t)bz * N_ + r0], s0);
                atomicAdd(&normSel[(size_t)bz * N_ + r1], s1);
            }
        }
    } else if (EPI == 1) {
        __nv_bfloat16* Cbb = Csel + (size_t)bz * sC;
        const float* qn2 = normSel + (size_t)bz * N_;
        const float* kn2 = biasSel + (size_t)bz * N_;
        float* rsumG = g_rsum + (size_t)bz * N_;
        float sc[8];
        #pragma unroll
        for (int nt = 0; nt < 4; nt++) {
            int c = cbase + nt * 8;
            sc[nt * 2]     = rsqrtf(__ldg(kn2 + c));
            sc[nt * 2 + 1] = rsqrtf(__ldg(kn2 + c + 1));
        }
        #pragma unroll
        for (int mt = 0; mt < 4; mt++) {
            int r0 = rbase + mt * 16, r1 = r0 + 8;
            float sr0 = rsqrtf(__ldg(qn2 + r0));
            float sr1 = rsqrtf(__ldg(qn2 + r1));
            float s0 = 0.f, s1 = 0.f;
            #pragma unroll
            for (int nt = 0; nt < 4; nt++) {
                int c = cbase + nt * 8;
                float v00 = __expf(acc[mt][nt][0] * sr0 * sc[nt * 2]);
                float v01 = __expf(acc[mt][nt][1] * sr0 * sc[nt * 2 + 1]);
                float v10 = __expf(acc[mt][nt][2] * sr1 * sc[nt * 2]);
                float v11 = __expf(acc[mt][nt][3] * sr1 * sc[nt * 2 + 1]);
                s0 += v00 + v01;
                s1 += v10 + v11;
                *(__nv_bfloat162*)(Cbb + (size_t)r0 * ldc + c) = __floats2bfloat162_rn(v00, v01);
                *(__nv_bfloat162*)(Cbb + (size_t)r1 * ldc + c) = __floats2bfloat162_rn(v10, v11);
            }
            s0 += __shfl_xor_sync(0xffffffffu, s0, 1);
            s0 += __shfl_xor_sync(0xffffffffu, s0, 2);
            s1 += __shfl_xor_sync(0xffffffffu, s1, 1);
            s1 += __shfl_xor_sync(0xffffffffu, s1, 2);
            if (tig == 0) {
                atomicAdd(&rsumG[r0], s0);
                atomicAdd(&rsumG[r1], s1);
            }
        }
    } else {
        const float gm = gptr[0];
        const __nv_bfloat16* Xp = Xb + (size_t)bz * sX;
        const float* rsumG = g_rsum + (size_t)bz * N_;
        float lsum = 0.f;
        unsigned lcnt = 0;
        #pragma unroll
        for (int mt = 0; mt < 4; mt++) {
            int r0 = rbase + mt * 16, r1 = r0 + 8;
            bool ok0 = r0 < nact, ok1 = r1 < nact;
            int s0i = ok0 ? g_idx[bz * N_ + r0] : 0;
            int s1i = ok1 ? g_idx[bz * N_ + r1] : 0;
            float gi0 = ok0 ? gm / __ldg(rsumG + r0) : 0.f;
            float gi1 = ok1 ? gm / __ldg(rsumG + r1) : 0.f;
            const __nv_bfloat16* xr0 = Xp + (size_t)s0i * ldc;
            const __nv_bfloat16* xr1 = Xp + (size_t)s1i * ldc;
            #pragma unroll
            for (int nt = 0; nt < 4; nt++) {
                int c = cbase + nt * 8;
                if (ok0) {
                    __nv_bfloat162 x0 = *(const __nv_bfloat162*)(xr0 + c);
                    float d0 = __bfloat162float(x0.x) - gi0 * acc[mt][nt][0];
                    float d1 = __bfloat162float(x0.y) - gi0 * acc[mt][nt][1];
                    float r00 = d0 * d0, r01 = d1 * d1;
                    lsum += r00 + r01;
                    lcnt += (r00 != 0.f) + (r01 != 0.f);
                }
                if (ok1) {
                    __nv_bfloat162 x1 = *(const __nv_bfloat162*)(xr1 + c);
                    float d2 = __bfloat162float(x1.x) - gi1 * acc[mt][nt][2];
                    float d3 = __bfloat162float(x1.y) - gi1 * acc[mt][nt][3];
                    float r10 = d2 * d2, r11 = d3 * d3;
                    lsum += r10 + r11;
                    lcnt += (r10 != 0.f) + (r11 != 0.f);
                }
            }
        }
        #pragma unroll
        for (int o = 16; o > 0; o >>= 1) {
            lsum += __shfl_down_sync(0xffffffffu, lsum, o);
            lcnt += __shfl_down_sync(0xffffffffu, lcnt, o);
        }
        if (lane == 0) {
            atomicAdd(&g_sum, (double)lsum);
            atomicAdd(&g_cnt, (unsigned long long)lcnt);
        }
    }
}

__global__ void finalize_kernel(float* out) {
    out[0] = (float)(g_sum / (double)g_cnt);
}

// ---------------- launch --------------------------------------------------------
extern "C" void kernel_launch(void* const* d_in, const int* in_sizes, int n_in,
                              void* d_out, int out_size)
{
    const float* x     = (const float*)d_in[0];
    const float* cam   = (const float*)d_in[1];
    const float* Wq    = (const float*)d_in[2];
    const float* bq    = (const float*)d_in[3];
    const float* Wk    = (const float*)d_in[4];
    const float* bk    = (const float*)d_in[5];
    const float* gamma = (const float*)d_in[6];

    cudaFuncSetAttribute(mma_gemm<0>, cudaFuncAttributeMaxDynamicSharedMemorySize, SMEM_DYN);
    cudaFuncSetAttribute(mma_gemm<1>, cudaFuncAttributeMaxDynamicSharedMemorySize, SMEM_DYN);
    cudaFuncSetAttribute(mma_gemm<2>, cudaFuncAttributeMaxDynamicSharedMemorySize, SMEM_DYN);

    __nv_bfloat16 *pxt, *pxb, *pwq, *pwk, *pqr, *pkr, *pattb;
    float *pqn2, *pkn2;
    cudaGetSymbolAddress((void**)&pxt,   g_xt);
    cudaGetSymbolAddress((void**)&pxb,   g_xb);
    cudaGetSymbolAddress((void**)&pwq,   g_wqb);
    cudaGetSymbolAddress((void**)&pwk,   g_wkb);
    cudaGetSymbolAddress((void**)&pqr,   g_qr);
    cudaGetSymbolAddress((void**)&pkr,   g_kr);
    cudaGetSymbolAddress((void**)&pattb, g_attb);
    cudaGetSymbolAddress((void**)&pqn2,  g_qn2);
    cudaGetSymbolAddress((void**)&pkn2,  g_kn2);

    const long long sNC = (long long)N_ * C_;
    const long long sCN = (long long)C_ * N_;
    const long long sNN = (long long)N_ * N_;

    zero_nact_kernel<<<1, 32>>>();
    preamble_kernel<<<MASK_BLOCKS + CVTW_BLOCKS, 256>>>(cam, Wq, Wk);
    cvt_x_kernel<<<dim3(N_ / 64, C_ / 32, B_), dim3(32, 8)>>>(x);

    // fused q & k: q gathers active rows; k full. rownorm2; bf16 out
    mma_gemm<0><<<dim3(2 * C_ / TN, N_ / TM, B_), 256, SMEM_DYN>>>(
        pxt, pwq, pqr, bq, nullptr, pqn2, nullptr,
        pwk, pkr, bk, pkn2,
        C_, C_, C_, C_, sNC, 0LL, sNC, 0LL);
    // attb[j,m] = exp(cos-logit); bf16 out; fp32 rowsums into g_rsum
    mma_gemm<1><<<dim3(N_ / TN, N_ / TM, B_), 256, SMEM_DYN>>>(
        pqr, pkr, pattb, pkn2, nullptr, pqn2, nullptr,
        nullptr, nullptr, nullptr, nullptr,
        C_, C_, C_, N_, sNC, sNC, sNN, 0LL);
    // loss: D[j,c] = (1/rsum[j]) * sum_m attb[j,m]*xb[c,m]; compare xt[g_idx[j],c]
    mma_gemm<2><<<dim3(C_ / TN, N_ / TM, B_), 256, SMEM_DYN>>>(
        pattb, pxb, nullptr, nullptr, pxt, nullptr, gamma,
        nullptr, nullptr, nullptr, nullptr,
        N_, N_, N_, C_, sNN, sCN, 0LL, sNC);

    finalize_kernel<<<1, 1>>>((float*)d_out);
}

// round 15
// speedup vs baseline: 1.0402x; 1.0059x over previous
#include <cuda_runtime.h>
#include <cuda_bf16.h>
#include <math.h>
#include <stdint.h>

#define B_   4
#define C_   2048
#define H_   48
#define N_   2304
#define CAM_ 384

#define TM   128
#define TN   128
#define TK   64
#define STAGE 32768                 /* A: 128*128B + B: 128*128B */
#define NSTAGE 3
#define SMEM_DYN (NSTAGE*STAGE + 1024)

#define MASK_BLOCKS ((B_ * N_ + 255) / 256)     /* 36  */
#define CVTW_BLOCKS (C_ * C_ / 1024)            /* 4096 */
#define EPI2_BLOCKS ((C_ / TN) * (N_ / TM) * B_)/* 1152 */

// ---------------- scratch (device globals) ----------------------------------
__device__ __nv_bfloat16 g_xb [B_ * C_ * N_];   // x bf16  [C,N]
__device__ __nv_bfloat16 g_xt [B_ * N_ * C_];   // x^T bf16 [N,C]
__device__ __nv_bfloat16 g_wqb[C_ * C_];
__device__ __nv_bfloat16 g_wkb[C_ * C_];
__device__ __nv_bfloat16 g_qr [B_ * N_ * C_];   // q, compacted rows
__device__ __nv_bfloat16 g_kr [B_ * N_ * C_];   // k, full rows
__device__ __nv_bfloat16 g_attb[B_ * N_ * N_];  // exp(logits), compacted rows
__device__ float g_qn2[B_ * N_];
__device__ float g_kn2[B_ * N_];
__device__ float g_rsum[B_ * N_];               // rowsum(exp), fp32
__device__ int   g_mflag[B_ * N_];
__device__ int   g_idx [B_ * N_];
__device__ int   g_nact[B_];                    // zero at entry (reset at end)
__device__ double g_sum;                        // zero at entry
__device__ unsigned long long g_cnt;            // zero at entry
__device__ unsigned int g_done;                 // zero at entry

// ---------------- helpers -----------------------------------------------------
__device__ __forceinline__ uint32_t smem_u32(const void* p) {
    uint32_t a;
    asm("{ .reg .u64 t; cvta.to.shared.u64 t, %1; cvt.u32.u64 %0, t; }"
        : "=r"(a) : "l"(p));
    return a;
}
__device__ __forceinline__ void cp_async16(uint32_t dst, const void* src) {
    asm volatile("cp.async.cg.shared.global [%0], [%1], 16;"
                 :: "r"(dst), "l"(src) : "memory");
}
__device__ __forceinline__ void cp_commit() {
    asm volatile("cp.async.commit_group;" ::: "memory");
}
__device__ __forceinline__ void cp_wait0() {
    asm volatile("cp.async.wait_group 0;" ::: "memory");
}
__device__ __forceinline__ void cp_wait1() {
    asm volatile("cp.async.wait_group 1;" ::: "memory");
}
__device__ __forceinline__ void ldsm_x4(uint32_t addr, uint32_t* r) {
    asm volatile("ldmatrix.sync.aligned.m8n8.x4.shared.b16 {%0,%1,%2,%3}, [%4];"
        : "=r"(r[0]), "=r"(r[1]), "=r"(r[2]), "=r"(r[3]) : "r"(addr));
}
__device__ __forceinline__ void mma_bf16(float* d, const uint32_t* a, const uint32_t* b) {
    asm volatile(
        "mma.sync.aligned.m16n8k16.row.col.f32.bf16.bf16.f32 "
        "{%0,%1,%2,%3}, {%4,%5,%6,%7}, {%8,%9}, {%0,%1,%2,%3};"
        : "+f"(d[0]), "+f"(d[1]), "+f"(d[2]), "+f"(d[3])
        : "r"(a[0]), "r"(a[1]), "r"(a[2]), "r"(a[3]), "r"(b[0]), "r"(b[1]));
}
#define SWZ(o) ((o) ^ (((o) >> 3) & 0x70))

// last-block finalize: write out, reset accumulators for next graph replay
__device__ __forceinline__ void finalize_tick(float* outp) {
    __threadfence();
    unsigned int old = atomicAdd(&g_done, 1u);
    if (old == EPI2_BLOCKS - 1) {
        __threadfence();
        outp[0] = (float)(g_sum / (double)g_cnt);
        g_sum = 0.0; g_cnt = 0ull; g_done = 0u;
        g_nact[0] = 0; g_nact[1] = 0; g_nact[2] = 0; g_nact[3] = 0;
    }
}

// ---------------- preamble: mask/compaction + W convert (one launch) -----------
__global__ void preamble_kernel(const float* __restrict__ cam,
                                const float* __restrict__ wq,
                                const float* __restrict__ wk) {
    if (blockIdx.x < MASK_BLOCKS) {
        int i = blockIdx.x * 256 + threadIdx.x;
        if (i >= B_ * N_) return;
        g_qn2[i] = 0.f; g_kn2[i] = 0.f; g_rsum[i] = 0.f;
        int b = i / N_, p = i % N_;
        int oy = p / H_, ox = p % H_;
        const float step = 383.0f / 47.0f;
        float sy = (float)oy * step, sx = (float)ox * step;
        int y0 = min(max((int)floorf(sy), 0), CAM_ - 1);
        int x0 = min(max((int)floorf(sx), 0), CAM_ - 1);
        int y1 = min(y0 + 1, CAM_ - 1), x1 = min(x0 + 1, CAM_ - 1);
        float wy = sy - (float)y0, wx = sx - (float)x0;
        const float* cb = cam + (size_t)b * CAM_ * CAM_;
        float v00 = cb[y0 * CAM_ + x0]; v00 = (v00 == 255.0f) ? 0.f : v00;
        float v01 = cb[y0 * CAM_ + x1]; v01 = (v01 == 255.0f) ? 0.f : v01;
        float v10 = cb[y1 * CAM_ + x0]; v10 = (v10 == 255.0f) ? 0.f : v10;
        float v11 = cb[y1 * CAM_ + x1]; v11 = (v11 == 255.0f) ? 0.f : v11;
        float val = (1.f - wy) * ((1.f - wx) * v00 + wx * v01)
                  + wy * ((1.f - wx) * v10 + wx * v11);
        if (val > 0.f) {
            g_mflag[i] = 1;
            int slot = atomicAdd(&g_nact[b], 1);
            g_idx[b * N_ + slot] = p;
        } else {
            g_mflag[i] = 0;
        }
    } else {
        int i = ((blockIdx.x - MASK_BLOCKS) * 256 + threadIdx.x) * 4;
        if (i < C_ * C_) {
            float4 a = *(const float4*)(wq + i);
            float4 b = *(const float4*)(wk + i);
            *(__nv_bfloat162*)(g_wqb + i)     = __floats2bfloat162_rn(a.x, a.y);
            *(__nv_bfloat162*)(g_wqb + i + 2) = __floats2bfloat162_rn(a.z, a.w);
            *(__nv_bfloat162*)(g_wkb + i)     = __floats2bfloat162_rn(b.x, b.y);
            *(__nv_bfloat162*)(g_wkb + i + 2) = __floats2bfloat162_rn(b.z, b.w);
        }
    }
}

// x fp32 [C,N] -> g_xb bf16 [C,N], g_xt bf16 [N,C]; masked-row loss, atomic-free
__global__ void cvt_x_kernel(const float* __restrict__ x) {
    __shared__ float tile[64][33];
    __shared__ float ssum[8][64];
    __shared__ int   scnt[8][64];
    __shared__ float rsum[64];
    __shared__ int   rcnt[64];
    const int b = blockIdx.z;
    const int n0 = blockIdx.x * 64, c0 = blockIdx.y * 32;
    const int tx = threadIdx.x, ty = threadIdx.y;   // 32 x 8
    const int tid = ty * 32 + tx;
    const float* xp = x + (size_t)b * C_ * N_;
    __nv_bfloat16* xbp = g_xb + (size_t)b * C_ * N_;
    __nv_bfloat16* xtp = g_xt + (size_t)b * N_ * C_;

    float s0 = 0.f, s1 = 0.f;
    int   k0 = 0,   k1 = 0;
    #pragma unroll
    for (int r = 0; r < 4; r++) {
        int c = c0 + ty + r * 8;
        float2 v = *(const float2*)(xp + (size_t)c * N_ + n0 + tx * 2);
        tile[tx * 2][ty + r * 8]     = v.x;
        tile[tx * 2 + 1][ty + r * 8] = v.y;
        *(__nv_bfloat162*)(xbp + (size_t)c * N_ + n0 + tx * 2) =
            __floats2bfloat162_rn(v.x, v.y);
        s0 += v.x * v.x; k0 += (v.x != 0.f);
        s1 += v.y * v.y; k1 += (v.y != 0.f);
    }
    ssum[ty][tx * 2] = s0; ssum[ty][tx * 2 + 1] = s1;
    scnt[ty][tx * 2] = k0; scnt[ty][tx * 2 + 1] = k1;
    __syncthreads();

    const int half = tx >> 4, cp2 = (tx & 15) * 2;
    #pragma unroll
    for (int r = 0; r < 4; r++) {
        int nl = ty * 2 + half + r * 16;
        *(__nv_bfloat162*)(xtp + (size_t)(n0 + nl) * C_ + c0 + cp2) =
            __floats2bfloat162_rn(tile[nl][cp2], tile[nl][cp2 + 1]);
    }
    if (tid < 64) {
        float s = 0.f; int k = 0;
        #pragma unroll
        for (int r = 0; r < 8; r++) { s += ssum[r][tid]; k += scnt[r][tid]; }
        int masked = (g_mflag[(size_t)b * N_ + n0 + tid] == 0);
        rsum[tid] = masked ? s : 0.f;
        rcnt[tid] = masked ? k : 0;
    }
    __syncthreads();
    for (int s = 32; s > 0; s >>= 1) {
        if (tid < s) { rsum[tid] += rsum[tid + s]; rcnt[tid] += rcnt[tid + s]; }
        __syncthreads();
    }
    if (tid == 0 && rcnt[0] > 0) {
        atomicAdd(&g_sum, (double)rsum[0]);
        atomicAdd(&g_cnt, (unsigned long long)rcnt[0]);
    }
}

// ---------------- HMMA GEMM 128x128x64, 3-stage single-sync mainloop -----------
// EPI 0: dual (q/k by blockIdx.x&1). q-half gathers A rows via g_idx; early-exit
//        beyond nact. v = acc + bias[col]; bf16 store; norm2[row] += v^2.
// EPI 1: v = exp(acc * rsqrt(qn2[row]) * rsqrt(kn2[col])); bf16 store;
//        g_rsum[row] += fp32 tile-row sums (atomics).
// EPI 2: loss: d = x - gamma / rsum[row] * acc; guarded to row < nact.
//        Last finishing block writes out[0] and resets launch state.
template <int EPI>
__global__ void __launch_bounds__(256, 2)
mma_gemm(const __nv_bfloat16* __restrict__ Ag, const __nv_bfloat16* __restrict__ Bg,
         __nv_bfloat16* __restrict__ Cb, const float* __restrict__ bias,
         const __nv_bfloat16* __restrict__ Xb, float* __restrict__ norm2,
         const float* __restrict__ gptr, float* __restrict__ outp,
         const __nv_bfloat16* __restrict__ Bg2, __nv_bfloat16* __restrict__ Cb2,
         const float* __restrict__ bias2, float* __restrict__ norm2b,
         int K, int lda, int ldb, int ldc,
         long long sA, long long sB, long long sC, long long sX)
{
    extern __shared__ char dsm[];
    const uint32_t dbase = (smem_u32(dsm) + 1023u) & ~1023u;

    const int tid  = threadIdx.x;
    const int lane = tid & 31;
    const int wid  = tid >> 5;
    const int wm   = wid & 1;
    const int wn   = wid >> 1;
    const int bz = blockIdx.z;
    const int m0 = blockIdx.y * TM;
    const int nact = g_nact[bz];

    int n0;
    const __nv_bfloat16* Bsel;
    __nv_bfloat16* Csel;
    const float* biasSel;
    float* normSel;
    bool gatherq = false;
    if (EPI == 0) {
        const int sel = blockIdx.x & 1;
        n0 = (blockIdx.x >> 1) * TN;
        Bsel = sel ? Bg2 : Bg;   Csel = sel ? Cb2 : Cb;
        biasSel = sel ? bias2 : bias;  normSel = sel ? norm2b : norm2;
        gatherq = (sel == 0);
        if (gatherq && m0 >= nact) return;
    } else {
        n0 = blockIdx.x * TN;
        Bsel = Bg; Csel = Cb; biasSel = bias; normSel = norm2;
        if (m0 >= nact) {
            if (EPI == 2 && tid == 0) finalize_tick(outp);
            return;
        }
    }

    const __nv_bfloat16* Bp = Bsel + (size_t)bz * sB + (size_t)n0 * ldb;

    const int t_m = tid >> 3;
    const int t_k = tid & 7;
    uint32_t cpo[4];
    const __nv_bfloat16* arow[4];
    const __nv_bfloat16* brow[4];
    #pragma unroll
    for (int i = 0; i < 4; i++) {
        cpo[i] = SWZ((uint32_t)((t_m + 32 * i) * 128 + t_k * 16));
        int rr = m0 + t_m + 32 * i;
        int src = rr;
        if (EPI == 0 && gatherq) src = g_idx[bz * N_ + rr];
        arow[i] = Ag + (size_t)bz * sA + (size_t)src * lda;
        brow[i] = Bp + (size_t)(t_m + 32 * i) * ldb;
    }

    uint32_t a_off[4], a_sw[4];
    #pragma unroll
    for (int mt = 0; mt < 4; mt++) {
        int r = wm * 64 + mt * 16 + (lane & 15);
        a_off[mt] = (uint32_t)r * 128u;
        a_sw[mt]  = (uint32_t)(r & 7) << 4;
    }
    const uint32_t a_hi = (uint32_t)(lane >> 4) << 4;
    uint32_t b_off[2], b_sw[2];
    #pragma unroll
    for (int p = 0; p < 2; p++) {
        int r = wn * 32 + (2 * p + (lane >> 4)) * 8 + (lane & 7);
        b_off[p] = (uint32_t)r * 128u;
        b_sw[p]  = (uint32_t)(r & 7) << 4;
    }
    const uint32_t b_hi = (uint32_t)((lane >> 3) & 1) << 4;

    float acc[4][4][4] = {};
    const int KT = K / TK;

    auto issue = [&](int t, int s) {
        uint32_t sb = dbase + (uint32_t)(s * STAGE);
        const int kt = t * TK;
        #pragma unroll
        for (int i = 0; i < 4; i++) {
            cp_async16(sb + cpo[i],         arow[i] + kt + t_k * 8);
            cp_async16(sb + 16384 + cpo[i], brow[i] + kt + t_k * 8);
        }
        cp_commit();
    };

    issue(0, 0);
    issue(1, 1);

    int s_cmp = 0, s_iss = 2;
    for (int t = 0; t < KT; t++) {
        if (t + 1 < KT) cp_wait1();
        else            cp_wait0();
        __syncthreads();
        if (t + 2 < KT) {
            issue(t + 2, s_iss);
            s_iss = (s_iss == 2) ? 0 : s_iss + 1;
        }

        const uint32_t As = dbase + (uint32_t)(s_cmp * STAGE);
        const uint32_t Bs = As + 16384;
        s_cmp = (s_cmp == 2) ? 0 : s_cmp + 1;
        #pragma unroll
        for (int ks = 0; ks < 4; ks++) {
            const uint32_t ko = (uint32_t)(ks * 32);
            uint32_t af[4][4], bf2[2][4];
            #pragma unroll
            for (int mt = 0; mt < 4; mt++)
                ldsm_x4(As + a_off[mt] + ((ko + a_hi) ^ a_sw[mt]), af[mt]);
            #pragma unroll
            for (int p = 0; p < 2; p++)
                ldsm_x4(Bs + b_off[p] + ((ko + b_hi) ^ b_sw[p]), bf2[p]);
            #pragma unroll
            for (int mt = 0; mt < 4; mt++)
                #pragma unroll
                for (int nt = 0; nt < 4; nt++)
                    mma_bf16(acc[mt][nt], af[mt], &bf2[nt >> 1][(nt & 1) * 2]);
        }
    }

    // ---------------- epilogue ----------------
    const int g   = lane >> 2;
    const int tig = lane & 3;
    const int rbase = m0 + wm * 64 + g;
    const int cbase = n0 + wn * 32 + tig * 2;

    if (EPI == 0) {
        __nv_bfloat16* Cbb = Csel + (size_t)bz * sC;
        #pragma unroll
        for (int mt = 0; mt < 4; mt++) {
            int r0 = rbase + mt * 16, r1 = r0 + 8;
            float s0 = 0.f, s1 = 0.f;
            #pragma unroll
            for (int nt = 0; nt < 4; nt++) {
                int c = cbase + nt * 8;
                float b0 = __ldg(biasSel + c), b1 = __ldg(biasSel + c + 1);
                float v00 = acc[mt][nt][0] + b0, v01 = acc[mt][nt][1] + b1;
                float v10 = acc[mt][nt][2] + b0, v11 = acc[mt][nt][3] + b1;
                s0 += v00 * v00 + v01 * v01;
                s1 += v10 * v10 + v11 * v11;
                *(__nv_bfloat162*)(Cbb + (size_t)r0 * ldc + c) = __floats2bfloat162_rn(v00, v01);
                *(__nv_bfloat162*)(Cbb + (size_t)r1 * ldc + c) = __floats2bfloat162_rn(v10, v11);
            }
            s0 += __shfl_xor_sync(0xffffffffu, s0, 1);
            s0 += __shfl_xor_sync(0xffffffffu, s0, 2);
            s1 += __shfl_xor_sync(0xffffffffu, s1, 1);
            s1 += __shfl_xor_sync(0xffffffffu, s1, 2);
            if (tig == 0) {
                atomicAdd(&normSel[(size_t)bz * N_ + r0], s0);
                atomicAdd(&normSel[(size_t)bz * N_ + r1], s1);
            }
        }
    } else if (EPI == 1) {
        __nv_bfloat16* Cbb = Csel + (size_t)bz * sC;
        const float* qn2 = normSel + (size_t)bz * N_;
        const float* kn2 = biasSel + (size_t)bz * N_;
        float* rsumG = g_rsum + (size_t)bz * N_;
        float sc[8];
        #pragma unroll
        for (int nt = 0; nt < 4; nt++) {
            int c = cbase + nt * 8;
            sc[nt * 2]     = rsqrtf(__ldg(kn2 + c));
            sc[nt * 2 + 1] = rsqrtf(__ldg(kn2 + c + 1));
        }
        #pragma unroll
        for (int mt = 0; mt < 4; mt++) {
            int r0 = rbase + mt * 16, r1 = r0 + 8;
            float sr0 = rsqrtf(__ldg(qn2 + r0));
            float sr1 = rsqrtf(__ldg(qn2 + r1));
            float s0 = 0.f, s1 = 0.f;
            #pragma unroll
            for (int nt = 0; nt < 4; nt++) {
                int c = cbase + nt * 8;
                float v00 = __expf(acc[mt][nt][0] * sr0 * sc[nt * 2]);
                float v01 = __expf(acc[mt][nt][1] * sr0 * sc[nt * 2 + 1]);
                float v10 = __expf(acc[mt][nt][2] * sr1 * sc[nt * 2]);
                float v11 = __expf(acc[mt][nt][3] * sr1 * sc[nt * 2 + 1]);
                s0 += v00 + v01;
                s1 += v10 + v11;
                *(__nv_bfloat162*)(Cbb + (size_t)r0 * ldc + c) = __floats2bfloat162_rn(v00, v01);
                *(__nv_bfloat162*)(Cbb + (size_t)r1 * ldc + c) = __floats2bfloat162_rn(v10, v11);
            }
            s0 += __shfl_xor_sync(0xffffffffu, s0, 1);
            s0 += __shfl_xor_sync(0xffffffffu, s0, 2);
            s1 += __shfl_xor_sync(0xffffffffu, s1, 1);
            s1 += __shfl_xor_sync(0xffffffffu, s1, 2);
            if (tig == 0) {
                atomicAdd(&rsumG[r0], s0);
                atomicAdd(&rsumG[r1], s1);
            }
        }
    } else {
        const float gm = gptr[0];
        const __nv_bfloat16* Xp = Xb + (size_t)bz * sX;
        const float* rsumG = g_rsum + (size_t)bz * N_;
        float lsum = 0.f;
        unsigned lcnt = 0;
        #pragma unroll
        for (int mt = 0; mt < 4; mt++) {
            int r0 = rbase + mt * 16, r1 = r0 + 8;
            bool ok0 = r0 < nact, ok1 = r1 < nact;
            int s0i = ok0 ? g_idx[bz * N_ + r0] : 0;
            int s1i = ok1 ? g_idx[bz * N_ + r1] : 0;
            float gi0 = ok0 ? gm / __ldg(rsumG + r0) : 0.f;
            float gi1 = ok1 ? gm / __ldg(rsumG + r1) : 0.f;
            const __nv_bfloat16* xr0 = Xp + (size_t)s0i * ldc;
            const __nv_bfloat16* xr1 = Xp + (size_t)s1i * ldc;
            #pragma unroll
            for (int nt = 0; nt < 4; nt++) {
                int c = cbase + nt * 8;
                if (ok0) {
                    __nv_bfloat162 x0 = *(const __nv_bfloat162*)(xr0 + c);
                    float d0 = __bfloat162float(x0.x) - gi0 * acc[mt][nt][0];
                    float d1 = __bfloat162float(x0.y) - gi0 * acc[mt][nt][1];
                    float r00 = d0 * d0, r01 = d1 * d1;
                    lsum += r00 + r01;
                    lcnt += (r00 != 0.f) + (r01 != 0.f);
                }
                if (ok1) {
                    __nv_bfloat162 x1 = *(const __nv_bfloat162*)(xr1 + c);
                    float d2 = __bfloat162float(x1.x) - gi1 * acc[mt][nt][2];
                    float d3 = __bfloat162float(x1.y) - gi1 * acc[mt][nt][3];
                    float r10 = d2 * d2, r11 = d3 * d3;
                    lsum += r10 + r11;
                    lcnt += (r10 != 0.f) + (r11 != 0.f);
                }
            }
        }
        #pragma unroll
        for (int o = 16; o > 0; o >>= 1) {
            lsum += __shfl_down_sync(0xffffffffu, lsum, o);
            lcnt += __shfl_down_sync(0xffffffffu, lcnt, o);
        }
        if (lane == 0) {
            atomicAdd(&g_sum, (double)lsum);
            atomicAdd(&g_cnt, (unsigned long long)lcnt);
        }
        __syncthreads();
        if (tid == 0) finalize_tick(outp);
    }
}

// ---------------- launch --------------------------------------------------------
extern "C" void kernel_launch(void* const* d_in, const int* in_sizes, int n_in,
                              void* d_out, int out_size)
{
    const float* x     = (const float*)d_in[0];
    const float* cam   = (const float*)d_in[1];
    const float* Wq    = (const float*)d_in[2];
    const float* bq    = (const float*)d_in[3];
    const float* Wk    = (const float*)d_in[4];
    const float* bk    = (const float*)d_in[5];
    const float* gamma = (const float*)d_in[6];

    cudaFuncSetAttribute(mma_gemm<0>, cudaFuncAttributeMaxDynamicSharedMemorySize, SMEM_DYN);
    cudaFuncSetAttribute(mma_gemm<1>, cudaFuncAttributeMaxDynamicSharedMemorySize, SMEM_DYN);
    cudaFuncSetAttribute(mma_gemm<2>, cudaFuncAttributeMaxDynamicSharedMemorySize, SMEM_DYN);

    __nv_bfloat16 *pxt, *pxb, *pwq, *pwk, *pqr, *pkr, *pattb;
    float *pqn2, *pkn2;
    cudaGetSymbolAddress((void**)&pxt,   g_xt);
    cudaGetSymbolAddress((void**)&pxb,   g_xb);
    cudaGetSymbolAddress((void**)&pwq,   g_wqb);
    cudaGetSymbolAddress((void**)&pwk,   g_wkb);
    cudaGetSymbolAddress((void**)&pqr,   g_qr);
    cudaGetSymbolAddress((void**)&pkr,   g_kr);
    cudaGetSymbolAddress((void**)&pattb, g_attb);
    cudaGetSymbolAddress((void**)&pqn2,  g_qn2);
    cudaGetSymbolAddress((void**)&pkn2,  g_kn2);

    const long long sNC = (long long)N_ * C_;
    const long long sCN = (long long)C_ * N_;
    const long long sNN = (long long)N_ * N_;

    preamble_kernel<<<MASK_BLOCKS + CVTW_BLOCKS, 256>>>(cam, Wq, Wk);
    cvt_x_kernel<<<dim3(N_ / 64, C_ / 32, B_), dim3(32, 8)>>>(x);

    // fused q & k: q gathers active rows; k full. rownorm2; bf16 out
    mma_gemm<0><<<dim3(2 * C_ / TN, N_ / TM, B_), 256, SMEM_DYN>>>(
        pxt, pwq, pqr, bq, nullptr, pqn2, nullptr, nullptr,
        pwk, pkr, bk, pkn2,
        C_, C_, C_, C_, sNC, 0LL, sNC, 0LL);
    // attb[j,m] = exp(cos-logit); bf16 out; fp32 rowsums into g_rsum
    mma_gemm<1><<<dim3(N_ / TN, N_ / TM, B_), 256, SMEM_DYN>>>(
        pqr, pkr, pattb, pkn2, nullptr, pqn2, nullptr, nullptr,
        nullptr, nullptr, nullptr, nullptr,
        C_, C_, C_, N_, sNC, sNC, sNN, 0LL);
    // loss + in-kernel finalize/reset: last block writes d_out
    mma_gemm<2><<<dim3(C_ / TN, N_ / TM, B_), 256, SMEM_DYN>>>(
        pattb, pxb, nullptr, nullptr, pxt, nullptr, gamma, (float*)d_out,
        nullptr, nullptr, nullptr, nullptr,
        N_, N_, N_, C_, sNN, sCN, 0LL, sNC);
}